// round 15
// baseline (speedup 1.0000x reference)
#include <cuda_runtime.h>
#include <math.h>
#include <stdint.h>

#define NN    4096
#define BB    16
#define KPER  205
#define KTOT  3280
#define LD2   208

// ---------------------------------------------------------------------------
// Scratch
// ---------------------------------------------------------------------------
constexpr size_t OFF_AT   = 0;
constexpr size_t OFF_ST   = OFF_AT   + 1048576;
constexpr size_t OFF_XA   = OFF_ST   + 1048576;
constexpr size_t OFF_XB   = OFF_XA   + 1048576;
constexpr size_t OFF_XNEW = OFF_XB   + 1048576;
constexpr size_t OFF_U    = OFF_XNEW + 1048576;
constexpr size_t OFF_V2   = OFF_U    + 1048576;
constexpr size_t OFF_SPT  = OFF_V2   + 1048576;
constexpr size_t OFF_M1   = OFF_SPT  + 851968;
constexpr size_t OFF_A2   = OFF_M1   + 851968;
constexpr size_t OFF_XSEL = OFF_A2   + 692224;
constexpr size_t OFF_XS2  = OFF_XSEL + 839680;
constexpr size_t OFF_XS3  = OFF_XS2  + 839680;
constexpr size_t OFF_CNT  = OFF_XS3  + 839680;
constexpr size_t OFF_V    = OFF_CNT  + 4096;
constexpr size_t OFF_AV   = OFF_V    + 4096;   // av/bm/w1t contiguous (12288)
constexpr size_t OFF_BM   = OFF_AV   + 4096;
constexpr size_t OFF_W1T  = OFF_BM   + 4096;
constexpr size_t OFF_FIT  = OFF_W1T  + 4096;
constexpr size_t OFF_CNT2 = OFF_FIT  + 4096;
constexpr size_t OFF_WLQ  = OFF_CNT2 + 4096;
constexpr size_t OFF_PART = OFF_WLQ  + 512;
constexpr size_t OFF_PERM = OFF_PART + 16384;
constexpr size_t BUF_TOT  = OFF_PERM + 4096;

__device__ __align__(256) float g_buf[BUF_TOT];

__device__ __forceinline__ float4 zf4() { return make_float4(0.f, 0.f, 0.f, 0.f); }

// ---------------------------------------------------------------------------
// Side stream + events for fork/join branches in the captured graph.
// Every side-stream op is downstream of a wait on an event recorded on the
// capturing stream (required for capture legality).
// ---------------------------------------------------------------------------
static cudaStream_t g_s2;
static cudaEvent_t  g_ev0, g_ev1, g_ev2, g_ev3;
namespace {
struct SideStreamInit {
    SideStreamInit() {
        cudaStreamCreateWithFlags(&g_s2, cudaStreamNonBlocking);
        cudaEventCreateWithFlags(&g_ev0, cudaEventDisableTiming);
        cudaEventCreateWithFlags(&g_ev1, cudaEventDisableTiming);
        cudaEventCreateWithFlags(&g_ev2, cudaEventDisableTiming);
        cudaEventCreateWithFlags(&g_ev3, cudaEventDisableTiming);
    }
};
SideStreamInit g_side_stream_init;
}

// ---------------------------------------------------------------------------
// Small kernels
// ---------------------------------------------------------------------------
__global__ void k_embed(const int* __restrict__ xt, const int* __restrict__ nd,
                        const float* __restrict__ et, const float* __restrict__ ed,
                        float* __restrict__ out)
{
    int i = blockIdx.x, t = threadIdx.x;
    out[i * 256 + t] = et[xt[i] * 256 + t] + ed[nd[i] * 256 + t];
}

// builds At AND the in-degree counts (cnt) in one pass over the edges
__global__ void k_buildA(const int* __restrict__ src, const int* __restrict__ dst,
                         float* __restrict__ At, float* __restrict__ cnt, int E)
{
    int e = blockIdx.x * blockDim.x + threadIdx.x;
    if (e >= E) return;
    int s = src[e], d = dst[e];
    int g = s >> 8, r = s & 255, c = d & 255;
    atomicAdd(&At[((size_t)g * 256 + c) * 256 + r], 1.0f);
    atomicAdd(&cnt[(g << 8) + c], 1.0f);
}

// wlq = p_Wlin @ watt[0:256]; wlq[256] = dot(p_blin, watt[0:256]) + p_batt
__global__ void k_wlq(const float* __restrict__ Wlin, const float* __restrict__ blin,
                      const float* __restrict__ watt, const float* __restrict__ batt,
                      float* __restrict__ wlq)
{
    int t = threadIdx.x;
    float s = 0.f;
    for (int j = 0; j < 256; j++) s += Wlin[t * 256 + j] * watt[j];
    wlq[t] = s;
    if (t == 0) {
        float c = 0.f;
        for (int j = 0; j < 256; j++) c += blin[j] * watt[j];
        wlq[256] = c + batt[0];
    }
}

// blocks 0..15 -> add self-loop diag; blocks 16.. -> v (8 nodes each)
__global__ void k_diagv(float* __restrict__ At, const float* __restrict__ watt,
                        const float* __restrict__ x, float* __restrict__ v)
{
    int b = blockIdx.x, t = threadIdx.x;
    if (b < BB) {
        At[((size_t)b * 256 + t) * 256 + t] += 1.0f;
    } else {
        int node = (b - BB) * 8 + (t >> 5);
        int lane = t & 31;
        const float* xx = x + (size_t)node * 256;
        float s = 0.f;
        for (int j = lane; j < 256; j += 32) s += xx[j] * watt[256 + j];
        for (int o = 16; o; o >>= 1) s += __shfl_xor_sync(0xffffffffu, s, o);
        if (!lane) v[node] = s;
    }
}

__global__ void k_att(const float* __restrict__ At, const float* __restrict__ x,
                      const float* __restrict__ v, const float* __restrict__ wlq,
                      float* __restrict__ St)
{
    int col = blockIdx.x, g = col >> 8, t = threadIdx.x;
    __shared__ int list[256];
    __shared__ int nnb;
    __shared__ float red[256];
    if (!t) nnb = 0;
    __syncthreads();
    float av = At[(size_t)col * 256 + t];
    if (av > 0.f) { int p = atomicAdd(&nnb, 1); list[p] = t; }
    __syncthreads();
    int n = nnb;
    const float* xg = x + ((size_t)(g << 8)) * 256;
    float m = -1e30f;
    int i = 0;
    for (; i + 4 <= n; i += 4) {
        float m0 = xg[list[i + 0] * 256 + t];
        float m1 = xg[list[i + 1] * 256 + t];
        float m2 = xg[list[i + 2] * 256 + t];
        float m3 = xg[list[i + 3] * 256 + t];
        m = fmaxf(m, fmaxf(fmaxf(m0, m1), fmaxf(m2, m3)));
    }
    for (; i < n; i++) m = fmaxf(m, xg[list[i] * 256 + t]);
    red[t] = m * wlq[t];
    __syncthreads();
    for (int o = 128; o; o >>= 1) { if (t < o) red[t] += red[t + o]; __syncthreads(); }
    float su = red[0] + wlq[256];
    __syncthreads();
    float vm = -1e30f;
    const float* vg = v + (g << 8);
    for (int j = t; j < n; j += 256) vm = fmaxf(vm, vg[list[j]]);
    red[t] = vm;
    __syncthreads();
    for (int o = 128; o; o >>= 1) { if (t < o) red[t] = fmaxf(red[t], red[t + o]); __syncthreads(); }
    float vmax = red[0];
    __syncthreads();
    float s = su + v[(g << 8) + t];
    s = s > 0.f ? s : 0.2f * s;
    float sm = su + vmax;
    sm = sm > 0.f ? sm : 0.2f * sm;
    float e = av > 0.f ? av * expf(s - sm) : 0.f;
    red[t] = e;
    __syncthreads();
    for (int o = 128; o; o >>= 1) { if (t < o) red[t] += red[t + o]; __syncthreads(); }
    St[(size_t)col * 256 + t] = e / red[0];
}

__global__ void k_fit(const float* __restrict__ At, const float* __restrict__ av,
                      const float* __restrict__ bm, const float* __restrict__ w1t,
                      const float* __restrict__ cnt, const float* __restrict__ b1,
                      const float* __restrict__ b3, float* __restrict__ fit)
{
    int node = (blockIdx.x * 256 + threadIdx.x) >> 5;
    int lane = threadIdx.x & 31;
    int g = node >> 8;
    const float* row = At + (size_t)node * 256;
    const float* ag = av + (g << 8);
    float s = 0.f;
    for (int j = lane; j < 256; j += 32) s += row[j] * ag[j];
    for (int o = 16; o; o >>= 1) s += __shfl_xor_sync(0xffffffffu, s, o);
    if (!lane) {
        float f = s - (cnt[node] + 1.f) * (bm[node] + b3[0]) + w1t[node] + b1[0];
        fit[node] = 1.f / (1.f + expf(-f));
    }
}

__global__ void k_topk(const float* __restrict__ fit, int* __restrict__ perm)
{
    int g = blockIdx.x, i = threadIdx.x;
    __shared__ float f[256];
    f[i] = fit[g * 256 + i];
    __syncthreads();
    float fi = f[i];
    int r = 0;
    for (int j = 0; j < 256; j++) {
        float fj = f[j];
        r += (fj > fi) || (fj == fi && j < i);
    }
    if (r < KPER) perm[g * KPER + r] = i;
}

__global__ void k_selspt(const int* __restrict__ perm, const float* __restrict__ xnew,
                         const float* __restrict__ fit, const float* __restrict__ St,
                         float* __restrict__ xsel, float* __restrict__ SpT)
{
    int k = blockIdx.x, t = threadIdx.x;
    int g = k / KPER, j = k - g * KPER;
    int gi = (g << 8) + perm[k];
    xsel[(size_t)k * 256 + t] = xnew[(size_t)gi * 256 + t] * fit[gi];
    SpT[((size_t)g * LD2 + j) * 256 + t] = St[(size_t)gi * 256 + t];
}

// k_head: part holds column SUMS per slot/graph; divide by row count here.
__global__ void k_head(const float* __restrict__ part, const float* __restrict__ W1,
                       const float* __restrict__ b1, const float* __restrict__ W2,
                       const float* __restrict__ b2, float* __restrict__ out)
{
    int g = blockIdx.x, t = threadIdx.x;
    __shared__ float hin[1024];
    __shared__ float h2[256];
    for (int k = t; k < 1024; k += 256) {
        int slot = k >> 8, feat = k & 255;
        float s = part[(size_t)(slot * 16 + g) * 256 + feat];
        hin[k] = s / (slot < 2 ? 256.f : (float)KPER);
    }
    __syncthreads();
    float s = 0.f;
    for (int k = 0; k < 1024; k++) s += hin[k] * W1[k * 256 + t];
    s += b1[t];
    h2[t] = s > 0.f ? s : 0.f;
    __syncthreads();
    if (t < 128) {
        float o = 0.f;
        for (int k = 0; k < 256; k++) o += h2[k] * W2[k * 128 + t];
        out[g * 128 + t] = o + b2[t];
    }
}

// ---------------------------------------------------------------------------
// GEMM cores (proven config): 32(q) x 64(r) x 16 tile, 64 threads, 8x4 micro,
// double-buffered. EPI==2: diag := 1 AND per-column nonzero count -> cnt2.
// ---------------------------------------------------------------------------
template <int MA, int MB, int EPI>
__global__ __launch_bounds__(64) void bgemm(
    const float* __restrict__ Ag, const float* __restrict__ Bg,
    float* __restrict__ Cg, float* __restrict__ cnt2,
    int P, int Q, int R, int ldA, int ldB, int ldC,
    int sA, int sB, int sC)
{
    int b = blockIdx.z;
    const float* A = Ag + (size_t)b * sA;
    const float* B = Bg + (size_t)b * sB;
    float* C = Cg + (size_t)b * sC;
    int q0 = blockIdx.y * 32, r0 = blockIdx.x * 64;
    int tid = threadIdx.x, tx = tid & 15, ty = tid >> 4;

    __shared__ float As[2][16][36];
    __shared__ float Bs[2][16][68];
    float4 ra0, ra1, rb[4];

    auto fetch = [&](int p0) {
        if (MA == 0) {
            int q1 = q0 + (tid >> 2);
            int pc = p0 + (tid & 3) * 4;
            ra0 = (q1 < Q) ? *(const float4*)&A[(size_t)q1 * ldA + pc] : zf4();
            ra1 = (q1 + 16 < Q) ? *(const float4*)&A[(size_t)(q1 + 16) * ldA + pc] : zf4();
        } else {
            int p1 = p0 + (tid >> 3);
            int qc = q0 + (tid & 7) * 4;
            ra0 = (p1 < P) ? *(const float4*)&A[(size_t)p1 * ldA + qc] : zf4();
            ra1 = (p1 + 8 < P) ? *(const float4*)&A[(size_t)(p1 + 8) * ldA + qc] : zf4();
        }
        if (MB == 0) {
            int p1 = p0 + (tid >> 4);
            int rc = r0 + (tid & 15) * 4;
#pragma unroll
            for (int w = 0; w < 4; w++)
                rb[w] = (p1 + 4 * w < P) ? *(const float4*)&B[(size_t)(p1 + 4 * w) * ldB + rc] : zf4();
        } else {
            int r1 = r0 + (tid >> 2);
            int pc = p0 + (tid & 3) * 4;
#pragma unroll
            for (int w = 0; w < 4; w++)
                rb[w] = (r1 + 16 * w < R) ? *(const float4*)&B[(size_t)(r1 + 16 * w) * ldB + pc] : zf4();
        }
    };
    auto store = [&](int buf) {
        if (MA == 0) {
            int row = tid >> 2, pc = (tid & 3) * 4;
            As[buf][pc + 0][row] = ra0.x; As[buf][pc + 1][row] = ra0.y;
            As[buf][pc + 2][row] = ra0.z; As[buf][pc + 3][row] = ra0.w;
            As[buf][pc + 0][row + 16] = ra1.x; As[buf][pc + 1][row + 16] = ra1.y;
            As[buf][pc + 2][row + 16] = ra1.z; As[buf][pc + 3][row + 16] = ra1.w;
        } else {
            int p = tid >> 3, qc = (tid & 7) * 4;
            *(float4*)&As[buf][p][qc] = ra0;
            *(float4*)&As[buf][p + 8][qc] = ra1;
        }
        if (MB == 0) {
            int p = tid >> 4, rc = (tid & 15) * 4;
#pragma unroll
            for (int w = 0; w < 4; w++)
                *(float4*)&Bs[buf][p + 4 * w][rc] = rb[w];
        } else {
            int row = tid >> 2, pc = (tid & 3) * 4;
#pragma unroll
            for (int w = 0; w < 4; w++) {
                Bs[buf][pc + 0][row + 16 * w] = rb[w].x;
                Bs[buf][pc + 1][row + 16 * w] = rb[w].y;
                Bs[buf][pc + 2][row + 16 * w] = rb[w].z;
                Bs[buf][pc + 3][row + 16 * w] = rb[w].w;
            }
        }
    };

    float acc[8][4] = {};
    fetch(0); store(0);
    __syncthreads();
    int nch = (P + 15) >> 4;
    for (int c = 0; c < nch; c++) {
        int cur = c & 1;
        if (c + 1 < nch) fetch((c + 1) * 16);
#pragma unroll
        for (int k = 0; k < 16; k++) {
            float4 a0 = *(const float4*)&As[cur][k][ty * 8];
            float4 a1 = *(const float4*)&As[cur][k][ty * 8 + 4];
            float4 b0 = *(const float4*)&Bs[cur][k][tx * 4];
            float avv[8] = {a0.x, a0.y, a0.z, a0.w, a1.x, a1.y, a1.z, a1.w};
            float bv[4] = {b0.x, b0.y, b0.z, b0.w};
#pragma unroll
            for (int i = 0; i < 8; i++)
#pragma unroll
                for (int j = 0; j < 4; j++) acc[i][j] = fmaf(avv[i], bv[j], acc[i][j]);
        }
        if (c + 1 < nch) store(cur ^ 1);
        __syncthreads();
    }

    float pc2[4] = {0.f, 0.f, 0.f, 0.f};
#pragma unroll
    for (int i = 0; i < 8; i++) {
        int q = q0 + ty * 8 + i;
        if (q >= Q) continue;
#pragma unroll
        for (int j = 0; j < 4; j++) {
            int r = r0 + tx * 4 + j;
            if (r >= R) continue;
            float v = acc[i][j];
            if (EPI == 2 && q == r) v = 1.f;
            if (EPI == 2) pc2[j] += (v != 0.f) ? 1.f : 0.f;
            C[(size_t)q * ldC + r] = v;
        }
    }
    if (EPI == 2) {
        float* cp = &As[0][0][0];
#pragma unroll
        for (int j = 0; j < 4; j++) cp[ty * 64 + tx * 4 + j] = pc2[j];
        __syncthreads();
        int r = r0 + tid;
        if (r < R) {
            float s = cp[tid] + cp[64 + tid] + cp[128 + tid] + cp[192 + tid];
            atomicAdd(&cnt2[(size_t)b * KPER + r], s);
        }
    }
}

// ---------------------------------------------------------------------------
// k_xnew: xnew = St @ x (per-graph 256x256x256), PLUS fused k_abm:
// av += xnew@W2, bm += xnew@W3, w1t += xnew@W1 (one atomicAdd per row per
// block; b3/b1 folded into k_fit).
// ---------------------------------------------------------------------------
__global__ __launch_bounds__(64) void k_xnew(
    const float* __restrict__ Stg, const float* __restrict__ Xg,
    float* __restrict__ XNg,
    const float* __restrict__ w1, const float* __restrict__ w2,
    const float* __restrict__ w3,
    float* __restrict__ av, float* __restrict__ bm, float* __restrict__ w1t)
{
    int b = blockIdx.z;
    const float* A = Stg + (size_t)b * 65536;
    const float* B = Xg + (size_t)b * 65536;
    float* C = XNg + (size_t)b * 65536;
    int q0 = blockIdx.y * 32, r0 = blockIdx.x * 64;
    int tid = threadIdx.x, tx = tid & 15, ty = tid >> 4;

    __shared__ float As[2][16][36];
    __shared__ float Bs[2][16][68];
    float4 ra0, ra1, rb[4];

    auto fetch = [&](int p0) {
        int q1 = q0 + (tid >> 2);
        int pc = p0 + (tid & 3) * 4;
        ra0 = *(const float4*)&A[(size_t)q1 * 256 + pc];
        ra1 = *(const float4*)&A[(size_t)(q1 + 16) * 256 + pc];
        int p1 = p0 + (tid >> 4);
        int rc = r0 + (tid & 15) * 4;
#pragma unroll
        for (int w = 0; w < 4; w++)
            rb[w] = *(const float4*)&B[(size_t)(p1 + 4 * w) * 256 + rc];
    };
    auto store = [&](int buf) {
        int row = tid >> 2, pc = (tid & 3) * 4;
        As[buf][pc + 0][row] = ra0.x; As[buf][pc + 1][row] = ra0.y;
        As[buf][pc + 2][row] = ra0.z; As[buf][pc + 3][row] = ra0.w;
        As[buf][pc + 0][row + 16] = ra1.x; As[buf][pc + 1][row + 16] = ra1.y;
        As[buf][pc + 2][row + 16] = ra1.z; As[buf][pc + 3][row + 16] = ra1.w;
        int p = tid >> 4, rc2 = (tid & 15) * 4;
#pragma unroll
        for (int w = 0; w < 4; w++)
            *(float4*)&Bs[buf][p + 4 * w][rc2] = rb[w];
    };

    float acc[8][4] = {};
    fetch(0); store(0);
    __syncthreads();
    for (int c = 0; c < 16; c++) {
        int cur = c & 1;
        if (c + 1 < 16) fetch((c + 1) * 16);
#pragma unroll
        for (int k = 0; k < 16; k++) {
            float4 a0 = *(const float4*)&As[cur][k][ty * 8];
            float4 a1 = *(const float4*)&As[cur][k][ty * 8 + 4];
            float4 b0 = *(const float4*)&Bs[cur][k][tx * 4];
            float avv[8] = {a0.x, a0.y, a0.z, a0.w, a1.x, a1.y, a1.z, a1.w};
            float bv[4] = {b0.x, b0.y, b0.z, b0.w};
#pragma unroll
            for (int i = 0; i < 8; i++)
#pragma unroll
                for (int j = 0; j < 4; j++) acc[i][j] = fmaf(avv[i], bv[j], acc[i][j]);
        }
        if (c + 1 < 16) store(cur ^ 1);
        __syncthreads();
    }

    float w1v[4], w2v[4], w3v[4];
#pragma unroll
    for (int j = 0; j < 4; j++) {
        int r = r0 + tx * 4 + j;
        w1v[j] = w1[r]; w2v[j] = w2[r]; w3v[j] = w3[r];
    }

#pragma unroll
    for (int i = 0; i < 8; i++) {
        int q = q0 + ty * 8 + i;
        float p1 = 0.f, p2 = 0.f, p3 = 0.f;
#pragma unroll
        for (int j = 0; j < 4; j++) {
            int r = r0 + tx * 4 + j;
            float v = acc[i][j];
            C[(size_t)q * 256 + r] = v;
            p1 = fmaf(v, w1v[j], p1);
            p2 = fmaf(v, w2v[j], p2);
            p3 = fmaf(v, w3v[j], p3);
        }
#pragma unroll
        for (int o = 8; o; o >>= 1) {
            p1 += __shfl_xor_sync(0xffffffffu, p1, o);
            p2 += __shfl_xor_sync(0xffffffffu, p2, o);
            p3 += __shfl_xor_sync(0xffffffffu, p3, o);
        }
        if (tx == 0) {
            int node = (b << 8) + q;
            atomicAdd(&w1t[node], p1);
            atomicAdd(&av[node], p2);
            atomicAdd(&bm[node], p3);
        }
    }
}

// k_w2: U = X@Wr, V = X@Wo + br. Grid (8, ceil(M/32)); x<4 -> Wr/U else Wo/V.
__global__ __launch_bounds__(64) void k_w2(
    const float* __restrict__ X,
    const float* __restrict__ Wr, const float* __restrict__ Wo,
    const float* __restrict__ br,
    float* __restrict__ U, float* __restrict__ V, int M)
{
    int sel = blockIdx.x >> 2;
    int r0 = (blockIdx.x & 3) * 64, q0 = blockIdx.y * 32;
    const float* W = sel ? Wo : Wr;
    float* O = sel ? V : U;
    int tid = threadIdx.x, tx = tid & 15, ty = tid >> 4;

    __shared__ float As[2][16][36];
    __shared__ float Bs[2][16][68];
    float4 ra0, ra1, rb[4];

    auto fetch = [&](int p0) {
        int q1 = q0 + (tid >> 2);
        int pc = p0 + (tid & 3) * 4;
        ra0 = (q1 < M) ? *(const float4*)&X[(size_t)q1 * 256 + pc] : zf4();
        ra1 = (q1 + 16 < M) ? *(const float4*)&X[(size_t)(q1 + 16) * 256 + pc] : zf4();
        int p1 = p0 + (tid >> 4);
        int rc = r0 + (tid & 15) * 4;
#pragma unroll
        for (int w = 0; w < 4; w++)
            rb[w] = *(const float4*)&W[(size_t)(p1 + 4 * w) * 256 + rc];
    };
    auto store = [&](int buf) {
        int row = tid >> 2, pc = (tid & 3) * 4;
        As[buf][pc + 0][row] = ra0.x; As[buf][pc + 1][row] = ra0.y;
        As[buf][pc + 2][row] = ra0.z; As[buf][pc + 3][row] = ra0.w;
        As[buf][pc + 0][row + 16] = ra1.x; As[buf][pc + 1][row + 16] = ra1.y;
        As[buf][pc + 2][row + 16] = ra1.z; As[buf][pc + 3][row + 16] = ra1.w;
        int p = tid >> 4, rc2 = (tid & 15) * 4;
#pragma unroll
        for (int w = 0; w < 4; w++)
            *(float4*)&Bs[buf][p + 4 * w][rc2] = rb[w];
    };

    float acc[8][4] = {};
    fetch(0); store(0);
    __syncthreads();
    for (int c = 0; c < 16; c++) {
        int cur = c & 1;
        if (c + 1 < 16) fetch((c + 1) * 16);
#pragma unroll
        for (int k = 0; k < 16; k++) {
            float4 a0 = *(const float4*)&As[cur][k][ty * 8];
            float4 a1 = *(const float4*)&As[cur][k][ty * 8 + 4];
            float4 b0 = *(const float4*)&Bs[cur][k][tx * 4];
            float avv[8] = {a0.x, a0.y, a0.z, a0.w, a1.x, a1.y, a1.z, a1.w};
            float bv[4] = {b0.x, b0.y, b0.z, b0.w};
#pragma unroll
            for (int i = 0; i < 8; i++)
#pragma unroll
                for (int j = 0; j < 4; j++) acc[i][j] = fmaf(avv[i], bv[j], acc[i][j]);
        }
        if (c + 1 < 16) store(cur ^ 1);
        __syncthreads();
    }

#pragma unroll
    for (int i = 0; i < 8; i++) {
        int q = q0 + ty * 8 + i;
        if (q >= M) continue;
#pragma unroll
        for (int j = 0; j < 4; j++) {
            int r = r0 + tx * 4 + j;
            float v = acc[i][j];
            if (sel) v += br[r];
            O[(size_t)q * 256 + r] = v;
        }
    }
}

// ---------------------------------------------------------------------------
// k_adj: Y[q][r] = relu( (sum_p Aop(p,q) U[p][r]) / max(S[q],1) + V[q][r] )
// PLUS fused column-sum pooling into part[slot][g][r].
// ---------------------------------------------------------------------------
template <int MA>
__global__ __launch_bounds__(64) void k_adj(
    const float* __restrict__ Ag, const float* __restrict__ Ug,
    const float* __restrict__ Vg, const float* __restrict__ Sg,
    float* __restrict__ Yg, float* __restrict__ part, int slot,
    int P, int Q, int ldA, int sA, int sM, int sS)
{
    int b = blockIdx.z;
    const float* A = Ag + (size_t)b * sA;
    const float* U = Ug + (size_t)b * sM;
    const float* V = Vg + (size_t)b * sM;
    const float* S = Sg + (size_t)b * sS;
    float* Y = Yg + (size_t)b * sM;
    int q0 = blockIdx.y * 32, r0 = blockIdx.x * 64;
    int tid = threadIdx.x, tx = tid & 15, ty = tid >> 4;

    __shared__ float As[2][16][36];
    __shared__ float Bs[2][16][68];
    __shared__ float pools[4][64];
    float4 ra0, ra1, rb[4];

    auto fetch = [&](int p0) {
        if (MA == 0) {
            int q1 = q0 + (tid >> 2);
            int pc = p0 + (tid & 3) * 4;
            ra0 = (q1 < Q) ? *(const float4*)&A[(size_t)q1 * ldA + pc] : zf4();
            ra1 = (q1 + 16 < Q) ? *(const float4*)&A[(size_t)(q1 + 16) * ldA + pc] : zf4();
        } else {
            int p1 = p0 + (tid >> 3);
            int qc = q0 + (tid & 7) * 4;
            ra0 = (p1 < P) ? *(const float4*)&A[(size_t)p1 * ldA + qc] : zf4();
            ra1 = (p1 + 8 < P) ? *(const float4*)&A[(size_t)(p1 + 8) * ldA + qc] : zf4();
        }
        int p1 = p0 + (tid >> 4);
        int rc = r0 + (tid & 15) * 4;
#pragma unroll
        for (int w = 0; w < 4; w++)
            rb[w] = (p1 + 4 * w < P) ? *(const float4*)&U[(size_t)(p1 + 4 * w) * 256 + rc] : zf4();
    };
    auto store = [&](int buf) {
        if (MA == 0) {
            int row = tid >> 2, pc = (tid & 3) * 4;
            As[buf][pc + 0][row] = ra0.x; As[buf][pc + 1][row] = ra0.y;
            As[buf][pc + 2][row] = ra0.z; As[buf][pc + 3][row] = ra0.w;
            As[buf][pc + 0][row + 16] = ra1.x; As[buf][pc + 1][row + 16] = ra1.y;
            As[buf][pc + 2][row + 16] = ra1.z; As[buf][pc + 3][row + 16] = ra1.w;
        } else {
            int p = tid >> 3, qc = (tid & 7) * 4;
            *(float4*)&As[buf][p][qc] = ra0;
            *(float4*)&As[buf][p + 8][qc] = ra1;
        }
        int p = tid >> 4, rc2 = (tid & 15) * 4;
#pragma unroll
        for (int w = 0; w < 4; w++)
            *(float4*)&Bs[buf][p + 4 * w][rc2] = rb[w];
    };

    float acc[8][4] = {};
    fetch(0); store(0);
    __syncthreads();
    int nch = (P + 15) >> 4;
    for (int c = 0; c < nch; c++) {
        int cur = c & 1;
        if (c + 1 < nch) fetch((c + 1) * 16);
#pragma unroll
        for (int k = 0; k < 16; k++) {
            float4 a0 = *(const float4*)&As[cur][k][ty * 8];
            float4 a1 = *(const float4*)&As[cur][k][ty * 8 + 4];
            float4 b0 = *(const float4*)&Bs[cur][k][tx * 4];
            float avv[8] = {a0.x, a0.y, a0.z, a0.w, a1.x, a1.y, a1.z, a1.w};
            float bv[4] = {b0.x, b0.y, b0.z, b0.w};
#pragma unroll
            for (int i = 0; i < 8; i++)
#pragma unroll
                for (int j = 0; j < 4; j++) acc[i][j] = fmaf(avv[i], bv[j], acc[i][j]);
        }
        if (c + 1 < nch) store(cur ^ 1);
        __syncthreads();
    }

    float psum[4] = {0.f, 0.f, 0.f, 0.f};
#pragma unroll
    for (int i = 0; i < 8; i++) {
        int q = q0 + ty * 8 + i;
        if (q >= Q) continue;
        float d = fmaxf(S[q], 1.f);
#pragma unroll
        for (int j = 0; j < 4; j++) {
            int r = r0 + tx * 4 + j;
            float v = acc[i][j] / d + V[(size_t)q * 256 + r];
            v = v > 0.f ? v : 0.f;
            Y[(size_t)q * 256 + r] = v;
            psum[j] += v;
        }
    }
#pragma unroll
    for (int j = 0; j < 4; j++) pools[ty][tx * 4 + j] = psum[j];
    __syncthreads();
    float colsum = pools[0][tid] + pools[1][tid] + pools[2][tid] + pools[3][tid];
    atomicAdd(&part[(size_t)(slot * 16 + b) * 256 + r0 + tid], colsum);
}

// ---------------------------------------------------------------------------
extern "C" void kernel_launch(void* const* d_in, const int* in_sizes, int n_in,
                              void* d_out, int out_size)
{
    float* buf = nullptr;
    cudaGetSymbolAddress((void**)&buf, g_buf);

    float* At   = buf + OFF_AT;
    float* St   = buf + OFF_ST;
    float* xa   = buf + OFF_XA;
    float* xb   = buf + OFF_XB;
    float* xnew = buf + OFF_XNEW;
    float* Ubuf = buf + OFF_U;
    float* Vbuf = buf + OFF_V2;
    float* SpT  = buf + OFF_SPT;
    float* M1   = buf + OFF_M1;
    float* A2   = buf + OFF_A2;
    float* xsel = buf + OFF_XSEL;
    float* xs2  = buf + OFF_XS2;
    float* xs3  = buf + OFF_XS3;
    float* cnt  = buf + OFF_CNT;
    float* vv   = buf + OFF_V;
    float* av   = buf + OFF_AV;
    float* bm   = buf + OFF_BM;
    float* w1t  = buf + OFF_W1T;
    float* fit  = buf + OFF_FIT;
    float* cnt2 = buf + OFF_CNT2;
    float* wlq  = buf + OFF_WLQ;
    float* part = buf + OFF_PART;
    int*   perm = (int*)(buf + OFF_PERM);

    const int*   x_type   = (const int*)d_in[0];
    const int*   node_dep = (const int*)d_in[1];
    const int*   eidx     = (const int*)d_in[2];
    const float* emb_type = (const float*)d_in[3];
    const float* emb_dep  = (const float*)d_in[4];
    const float* c0_Wr = (const float*)d_in[5];
    const float* c0_br = (const float*)d_in[6];
    const float* c0_Wo = (const float*)d_in[7];
    const float* c1_Wr = (const float*)d_in[8];
    const float* c1_br = (const float*)d_in[9];
    const float* c1_Wo = (const float*)d_in[10];
    const float* c2_Wr = (const float*)d_in[11];
    const float* c2_br = (const float*)d_in[12];
    const float* c2_Wo = (const float*)d_in[13];
    const float* c3_Wr = (const float*)d_in[14];
    const float* c3_br = (const float*)d_in[15];
    const float* c3_Wo = (const float*)d_in[16];
    const float* p_Wlin = (const float*)d_in[17];
    const float* p_blin = (const float*)d_in[18];
    const float* p_Watt = (const float*)d_in[19];
    const float* p_batt = (const float*)d_in[20];
    const float* le_W1 = (const float*)d_in[21];
    const float* le_b1 = (const float*)d_in[22];
    const float* le_W2 = (const float*)d_in[23];
    const float* le_W3 = (const float*)d_in[24];
    const float* le_b3 = (const float*)d_in[25];
    const float* lin1_W = (const float*)d_in[26];
    const float* lin1_b = (const float*)d_in[27];
    const float* pred_W = (const float*)d_in[28];
    const float* pred_b = (const float*)d_in[29];

    int E = in_sizes[2] / 2;
    const int* src = eidx;
    const int* dst = eidx + E;

    dim3 gW(8, 128);               // M=4096 / 32
    dim3 gWK(8, 103);              // M=3280
    dim3 gAdj(4, 8, BB);           // Q=256 / 32
    dim3 gAdjK(4, 7, BB);          // Q=205
    dim3 gFull(4, 8, BB);
    dim3 gM1(4, 8, BB);

    // ---- prologue (default stream) ----
    cudaMemsetAsync(At, 0, (size_t)BB * 65536 * sizeof(float), 0);
    cudaMemsetAsync(cnt, 0, NN * sizeof(float), 0);
    cudaMemsetAsync(av, 0, 3 * NN * sizeof(float), 0);    // av/bm/w1t
    cudaMemsetAsync(cnt2, 0, 4096 * sizeof(float), 0);
    cudaMemsetAsync(part, 0, 4 * BB * 256 * sizeof(float), 0);
    k_embed<<<NN, 256>>>(x_type, node_dep, emb_type, emb_dep, xa);

    // FORK 1: side stream enters capture via ev0; runs wlq then k_w2-L0.
    cudaEventRecord(g_ev0, 0);
    cudaStreamWaitEvent(g_s2, g_ev0, 0);
    k_wlq<<<1, 256, 0, g_s2>>>(p_Wlin, p_blin, p_Watt, p_batt, wlq);
    k_w2<<<gW, 64, 0, g_s2>>>(xa, c0_Wr, c0_Wo, c0_br, Ubuf, Vbuf, NN);
    cudaEventRecord(g_ev1, g_s2);

    k_buildA<<<(E + 255) / 256, 256>>>(src, dst, At, cnt, E);

    cudaStreamWaitEvent(0, g_ev1, 0);   // join (wlq + w2-L0 done)
    k_adj<0><<<gAdj, 64>>>(At, Ubuf, Vbuf, cnt, xb, part, 0,
                           256, 256, 256, 65536, 65536, 256);

    // layer 1 (serial)
    k_w2<<<gW, 64>>>(xb, c1_Wr, c1_Wo, c1_br, Ubuf, Vbuf, NN);
    k_adj<0><<<gAdj, 64>>>(At, Ubuf, Vbuf, cnt, xa, part, 1,
                           256, 256, 256, 65536, 65536, 256);

    // ASAP
    k_diagv<<<BB + NN / 8, 256>>>(At, p_Watt, xa, vv);
    k_att<<<NN, 256>>>(At, xa, vv, wlq, St);
    k_xnew<<<gFull, 64>>>(St, xa, xnew, le_W1, le_W2, le_W3, av, bm, w1t);
    k_fit<<<NN / 8, 256>>>(At, av, bm, w1t, cnt, le_b1, le_b3, fit);
    k_topk<<<BB, 256>>>(fit, perm);
    k_selspt<<<KTOT, 256>>>(perm, xnew, fit, St, xsel, SpT);

    // FORK 2: k_w2-L2 needs only xsel; M1/A2 chain is independent of it.
    cudaEventRecord(g_ev2, 0);
    cudaStreamWaitEvent(g_s2, g_ev2, 0);
    k_w2<<<gWK, 64, 0, g_s2>>>(xsel, c2_Wr, c2_Wo, c2_br, Ubuf, Vbuf, KTOT);
    cudaEventRecord(g_ev3, g_s2);

    bgemm<1, 1, 0><<<gM1, 64>>>(At, SpT, M1, nullptr, 256, 256, KPER, 256, 256, LD2,
                                65536, LD2 * 256, 256 * LD2);
    bgemm<0, 0, 2><<<gAdjK, 64>>>(SpT, M1, A2, cnt2, 256, KPER, KPER, 256, LD2, LD2,
                                  LD2 * 256, 256 * LD2, LD2 * LD2);

    cudaStreamWaitEvent(0, g_ev3, 0);   // join
    k_adj<1><<<gAdjK, 64>>>(A2, Ubuf, Vbuf, cnt2, xs2, part, 2,
                            KPER, KPER, LD2, LD2 * LD2, KPER * 256, KPER);

    // layer 3 (serial)
    k_w2<<<gWK, 64>>>(xs2, c3_Wr, c3_Wo, c3_br, Ubuf, Vbuf, KTOT);
    k_adj<1><<<gAdjK, 64>>>(A2, Ubuf, Vbuf, cnt2, xs3, part, 3,
                            KPER, KPER, LD2, LD2 * LD2, KPER * 256, KPER);

    k_head<<<BB, 256>>>(part, lin1_W, lin1_b, pred_W, pred_b, (float*)d_out);
}

// round 16
// speedup vs baseline: 1.0229x; 1.0229x over previous
#include <cuda_runtime.h>
#include <math.h>
#include <stdint.h>

#define NN    4096
#define BB    16
#define KPER  205
#define KTOT  3280
#define LD2   208

// ---------------------------------------------------------------------------
// Scratch
// ---------------------------------------------------------------------------
constexpr size_t OFF_AT   = 0;
constexpr size_t OFF_ST   = OFF_AT   + 1048576;
constexpr size_t OFF_XA   = OFF_ST   + 1048576;
constexpr size_t OFF_XB   = OFF_XA   + 1048576;   // reused as M1full after L1
constexpr size_t OFF_XNEW = OFF_XB   + 1048576;
constexpr size_t OFF_U    = OFF_XNEW + 1048576;
constexpr size_t OFF_V2   = OFF_U    + 1048576;
constexpr size_t OFF_Z    = OFF_V2   + 1048576;   // 16*256*256 (old SPT+M1 span)
constexpr size_t OFF_A2   = OFF_Z    + 1703936;
constexpr size_t OFF_XSEL = OFF_A2   + 692224;
constexpr size_t OFF_XS2  = OFF_XSEL + 839680;
constexpr size_t OFF_XS3  = OFF_XS2  + 839680;
constexpr size_t OFF_CNT  = OFF_XS3  + 839680;
constexpr size_t OFF_V    = OFF_CNT  + 4096;
constexpr size_t OFF_AV   = OFF_V    + 4096;      // av/bm/w1t contiguous
constexpr size_t OFF_BM   = OFF_AV   + 4096;
constexpr size_t OFF_W1T  = OFF_BM   + 4096;
constexpr size_t OFF_FIT  = OFF_W1T  + 4096;
constexpr size_t OFF_CNT2 = OFF_FIT  + 4096;
constexpr size_t OFF_WLQ  = OFF_CNT2 + 4096;
constexpr size_t OFF_PART = OFF_WLQ  + 512;
constexpr size_t OFF_PERM = OFF_PART + 16384;
constexpr size_t BUF_TOT  = OFF_PERM + 4096;

__device__ __align__(256) float g_buf[BUF_TOT];

__device__ __forceinline__ float4 zf4() { return make_float4(0.f, 0.f, 0.f, 0.f); }

// ---------------------------------------------------------------------------
// Side stream + events (every side-stream op sits downstream of an event
// recorded on the capturing stream — capture-legal fork/join).
// ---------------------------------------------------------------------------
static cudaStream_t g_s2;
static cudaEvent_t  g_ev0, g_ev1, g_ev2, g_ev3, g_evT;
namespace {
struct SideStreamInit {
    SideStreamInit() {
        cudaStreamCreateWithFlags(&g_s2, cudaStreamNonBlocking);
        cudaEventCreateWithFlags(&g_ev0, cudaEventDisableTiming);
        cudaEventCreateWithFlags(&g_ev1, cudaEventDisableTiming);
        cudaEventCreateWithFlags(&g_ev2, cudaEventDisableTiming);
        cudaEventCreateWithFlags(&g_ev3, cudaEventDisableTiming);
        cudaEventCreateWithFlags(&g_evT, cudaEventDisableTiming);
    }
};
SideStreamInit g_side_stream_init;
}

// ---------------------------------------------------------------------------
// Small kernels
// ---------------------------------------------------------------------------
__global__ void k_embed(const int* __restrict__ xt, const int* __restrict__ nd,
                        const float* __restrict__ et, const float* __restrict__ ed,
                        float* __restrict__ out)
{
    int i = blockIdx.x, t = threadIdx.x;
    out[i * 256 + t] = et[xt[i] * 256 + t] + ed[nd[i] * 256 + t];
}

__global__ void k_buildA(const int* __restrict__ src, const int* __restrict__ dst,
                         float* __restrict__ At, float* __restrict__ cnt, int E)
{
    int e = blockIdx.x * blockDim.x + threadIdx.x;
    if (e >= E) return;
    int s = src[e], d = dst[e];
    int g = s >> 8, r = s & 255, c = d & 255;
    atomicAdd(&At[((size_t)g * 256 + c) * 256 + r], 1.0f);
    atomicAdd(&cnt[(g << 8) + c], 1.0f);
}

__global__ void k_wlq(const float* __restrict__ Wlin, const float* __restrict__ blin,
                      const float* __restrict__ watt, const float* __restrict__ batt,
                      float* __restrict__ wlq)
{
    int t = threadIdx.x;
    float s = 0.f;
    for (int j = 0; j < 256; j++) s += Wlin[t * 256 + j] * watt[j];
    wlq[t] = s;
    if (t == 0) {
        float c = 0.f;
        for (int j = 0; j < 256; j++) c += blin[j] * watt[j];
        wlq[256] = c + batt[0];
    }
}

__global__ void k_diagv(float* __restrict__ At, const float* __restrict__ watt,
                        const float* __restrict__ x, float* __restrict__ v)
{
    int b = blockIdx.x, t = threadIdx.x;
    if (b < BB) {
        At[((size_t)b * 256 + t) * 256 + t] += 1.0f;
    } else {
        int node = (b - BB) * 8 + (t >> 5);
        int lane = t & 31;
        const float* xx = x + (size_t)node * 256;
        float s = 0.f;
        for (int j = lane; j < 256; j += 32) s += xx[j] * watt[256 + j];
        for (int o = 16; o; o >>= 1) s += __shfl_xor_sync(0xffffffffu, s, o);
        if (!lane) v[node] = s;
    }
}

__global__ void k_att(const float* __restrict__ At, const float* __restrict__ x,
                      const float* __restrict__ v, const float* __restrict__ wlq,
                      float* __restrict__ St)
{
    int col = blockIdx.x, g = col >> 8, t = threadIdx.x;
    __shared__ int list[256];
    __shared__ int nnb;
    __shared__ float red[256];
    if (!t) nnb = 0;
    __syncthreads();
    float av = At[(size_t)col * 256 + t];
    if (av > 0.f) { int p = atomicAdd(&nnb, 1); list[p] = t; }
    __syncthreads();
    int n = nnb;
    const float* xg = x + ((size_t)(g << 8)) * 256;
    float m = -1e30f;
    int i = 0;
    for (; i + 4 <= n; i += 4) {
        float m0 = xg[list[i + 0] * 256 + t];
        float m1 = xg[list[i + 1] * 256 + t];
        float m2 = xg[list[i + 2] * 256 + t];
        float m3 = xg[list[i + 3] * 256 + t];
        m = fmaxf(m, fmaxf(fmaxf(m0, m1), fmaxf(m2, m3)));
    }
    for (; i < n; i++) m = fmaxf(m, xg[list[i] * 256 + t]);
    red[t] = m * wlq[t];
    __syncthreads();
    for (int o = 128; o; o >>= 1) { if (t < o) red[t] += red[t + o]; __syncthreads(); }
    float su = red[0] + wlq[256];
    __syncthreads();
    float vm = -1e30f;
    const float* vg = v + (g << 8);
    for (int j = t; j < n; j += 256) vm = fmaxf(vm, vg[list[j]]);
    red[t] = vm;
    __syncthreads();
    for (int o = 128; o; o >>= 1) { if (t < o) red[t] = fmaxf(red[t], red[t + o]); __syncthreads(); }
    float vmax = red[0];
    __syncthreads();
    float s = su + v[(g << 8) + t];
    s = s > 0.f ? s : 0.2f * s;
    float sm = su + vmax;
    sm = sm > 0.f ? sm : 0.2f * sm;
    float e = av > 0.f ? av * expf(s - sm) : 0.f;
    red[t] = e;
    __syncthreads();
    for (int o = 128; o; o >>= 1) { if (t < o) red[t] += red[t + o]; __syncthreads(); }
    St[(size_t)col * 256 + t] = e / red[0];
}

__global__ void k_fit(const float* __restrict__ At, const float* __restrict__ av,
                      const float* __restrict__ bm, const float* __restrict__ w1t,
                      const float* __restrict__ cnt, const float* __restrict__ b1,
                      const float* __restrict__ b3, float* __restrict__ fit)
{
    int node = (blockIdx.x * 256 + threadIdx.x) >> 5;
    int lane = threadIdx.x & 31;
    int g = node >> 8;
    const float* row = At + (size_t)node * 256;
    const float* ag = av + (g << 8);
    float s = 0.f;
    for (int j = lane; j < 256; j += 32) s += row[j] * ag[j];
    for (int o = 16; o; o >>= 1) s += __shfl_xor_sync(0xffffffffu, s, o);
    if (!lane) {
        float f = s - (cnt[node] + 1.f) * (bm[node] + b3[0]) + w1t[node] + b1[0];
        fit[node] = 1.f / (1.f + expf(-f));
    }
}

__global__ void k_topk(const float* __restrict__ fit, int* __restrict__ perm)
{
    int g = blockIdx.x, i = threadIdx.x;
    __shared__ float f[256];
    f[i] = fit[g * 256 + i];
    __syncthreads();
    float fi = f[i];
    int r = 0;
    for (int j = 0; j < 256; j++) {
        float fj = f[j];
        r += (fj > fi) || (fj == fi && j < i);
    }
    if (r < KPER) perm[g * KPER + r] = i;
}

// select: xsel only (SpT no longer needed — A2 gathered from Z)
__global__ void k_sel(const int* __restrict__ perm, const float* __restrict__ xnew,
                      const float* __restrict__ fit, float* __restrict__ xsel)
{
    int k = blockIdx.x, t = threadIdx.x;
    int g = k / KPER;
    int gi = (g << 8) + perm[k];
    xsel[(size_t)k * 256 + t] = xnew[(size_t)gi * 256 + t] * fit[gi];
}

// A2[i][j] = (i==j) ? 1 : Z[perm_i][perm_j]; cnt2[j] += (val != 0)
__global__ void k_a2(const int* __restrict__ perm, const float* __restrict__ Z,
                     float* __restrict__ A2, float* __restrict__ cnt2)
{
    int k = blockIdx.x;                   // 0..KTOT-1
    int g = k / KPER, i = k - g * KPER;
    int t = threadIdx.x;
    if (t >= KPER) return;
    const int* pg = perm + g * KPER;
    const float* Zr = Z + (size_t)g * 65536 + (size_t)pg[i] * 256;
    float v = (t == i) ? 1.f : Zr[pg[t]];
    A2[(size_t)g * LD2 * LD2 + (size_t)i * LD2 + t] = v;
    if (v != 0.f) atomicAdd(&cnt2[g * KPER + t], 1.f);
}

// k_head: part holds column SUMS per slot/graph; divide by row count here.
__global__ void k_head(const float* __restrict__ part, const float* __restrict__ W1,
                       const float* __restrict__ b1, const float* __restrict__ W2,
                       const float* __restrict__ b2, float* __restrict__ out)
{
    int g = blockIdx.x, t = threadIdx.x;
    __shared__ float hin[1024];
    __shared__ float h2[256];
    for (int k = t; k < 1024; k += 256) {
        int slot = k >> 8, feat = k & 255;
        float s = part[(size_t)(slot * 16 + g) * 256 + feat];
        hin[k] = s / (slot < 2 ? 256.f : (float)KPER);
    }
    __syncthreads();
    float s = 0.f;
    for (int k = 0; k < 1024; k++) s += hin[k] * W1[k * 256 + t];
    s += b1[t];
    h2[t] = s > 0.f ? s : 0.f;
    __syncthreads();
    if (t < 128) {
        float o = 0.f;
        for (int k = 0; k < 256; k++) o += h2[k] * W2[k * 128 + t];
        out[g * 128 + t] = o + b2[t];
    }
}

// ---------------------------------------------------------------------------
// GEMM core (proven config): 32(q) x 64(r) x 16 tile, 64 threads, 8x4 micro,
// double-buffered.
// ---------------------------------------------------------------------------
template <int MA, int MB>
__global__ __launch_bounds__(64) void bgemm(
    const float* __restrict__ Ag, const float* __restrict__ Bg,
    float* __restrict__ Cg,
    int P, int Q, int R, int ldA, int ldB, int ldC,
    int sA, int sB, int sC)
{
    int b = blockIdx.z;
    const float* A = Ag + (size_t)b * sA;
    const float* B = Bg + (size_t)b * sB;
    float* C = Cg + (size_t)b * sC;
    int q0 = blockIdx.y * 32, r0 = blockIdx.x * 64;
    int tid = threadIdx.x, tx = tid & 15, ty = tid >> 4;

    __shared__ float As[2][16][36];
    __shared__ float Bs[2][16][68];
    float4 ra0, ra1, rb[4];

    auto fetch = [&](int p0) {
        if (MA == 0) {
            int q1 = q0 + (tid >> 2);
            int pc = p0 + (tid & 3) * 4;
            ra0 = (q1 < Q) ? *(const float4*)&A[(size_t)q1 * ldA + pc] : zf4();
            ra1 = (q1 + 16 < Q) ? *(const float4*)&A[(size_t)(q1 + 16) * ldA + pc] : zf4();
        } else {
            int p1 = p0 + (tid >> 3);
            int qc = q0 + (tid & 7) * 4;
            ra0 = (p1 < P) ? *(const float4*)&A[(size_t)p1 * ldA + qc] : zf4();
            ra1 = (p1 + 8 < P) ? *(const float4*)&A[(size_t)(p1 + 8) * ldA + qc] : zf4();
        }
        if (MB == 0) {
            int p1 = p0 + (tid >> 4);
            int rc = r0 + (tid & 15) * 4;
#pragma unroll
            for (int w = 0; w < 4; w++)
                rb[w] = (p1 + 4 * w < P) ? *(const float4*)&B[(size_t)(p1 + 4 * w) * ldB + rc] : zf4();
        } else {
            int r1 = r0 + (tid >> 2);
            int pc = p0 + (tid & 3) * 4;
#pragma unroll
            for (int w = 0; w < 4; w++)
                rb[w] = (r1 + 16 * w < R) ? *(const float4*)&B[(size_t)(r1 + 16 * w) * ldB + pc] : zf4();
        }
    };
    auto store = [&](int buf) {
        if (MA == 0) {
            int row = tid >> 2, pc = (tid & 3) * 4;
            As[buf][pc + 0][row] = ra0.x; As[buf][pc + 1][row] = ra0.y;
            As[buf][pc + 2][row] = ra0.z; As[buf][pc + 3][row] = ra0.w;
            As[buf][pc + 0][row + 16] = ra1.x; As[buf][pc + 1][row + 16] = ra1.y;
            As[buf][pc + 2][row + 16] = ra1.z; As[buf][pc + 3][row + 16] = ra1.w;
        } else {
            int p = tid >> 3, qc = (tid & 7) * 4;
            *(float4*)&As[buf][p][qc] = ra0;
            *(float4*)&As[buf][p + 8][qc] = ra1;
        }
        if (MB == 0) {
            int p = tid >> 4, rc = (tid & 15) * 4;
#pragma unroll
            for (int w = 0; w < 4; w++)
                *(float4*)&Bs[buf][p + 4 * w][rc] = rb[w];
        } else {
            int row = tid >> 2, pc = (tid & 3) * 4;
#pragma unroll
            for (int w = 0; w < 4; w++) {
                Bs[buf][pc + 0][row + 16 * w] = rb[w].x;
                Bs[buf][pc + 1][row + 16 * w] = rb[w].y;
                Bs[buf][pc + 2][row + 16 * w] = rb[w].z;
                Bs[buf][pc + 3][row + 16 * w] = rb[w].w;
            }
        }
    };

    float acc[8][4] = {};
    fetch(0); store(0);
    __syncthreads();
    int nch = (P + 15) >> 4;
    for (int c = 0; c < nch; c++) {
        int cur = c & 1;
        if (c + 1 < nch) fetch((c + 1) * 16);
#pragma unroll
        for (int k = 0; k < 16; k++) {
            float4 a0 = *(const float4*)&As[cur][k][ty * 8];
            float4 a1 = *(const float4*)&As[cur][k][ty * 8 + 4];
            float4 b0 = *(const float4*)&Bs[cur][k][tx * 4];
            float avv[8] = {a0.x, a0.y, a0.z, a0.w, a1.x, a1.y, a1.z, a1.w};
            float bv[4] = {b0.x, b0.y, b0.z, b0.w};
#pragma unroll
            for (int i = 0; i < 8; i++)
#pragma unroll
                for (int j = 0; j < 4; j++) acc[i][j] = fmaf(avv[i], bv[j], acc[i][j]);
        }
        if (c + 1 < nch) store(cur ^ 1);
        __syncthreads();
    }

#pragma unroll
    for (int i = 0; i < 8; i++) {
        int q = q0 + ty * 8 + i;
        if (q >= Q) continue;
#pragma unroll
        for (int j = 0; j < 4; j++) {
            int r = r0 + tx * 4 + j;
            if (r >= R) continue;
            C[(size_t)q * ldC + r] = acc[i][j];
        }
    }
}

// ---------------------------------------------------------------------------
// k_xnew: xnew = St @ x (per-graph), PLUS fused le-dots into av/bm/w1t.
// ---------------------------------------------------------------------------
__global__ __launch_bounds__(64) void k_xnew(
    const float* __restrict__ Stg, const float* __restrict__ Xg,
    float* __restrict__ XNg,
    const float* __restrict__ w1, const float* __restrict__ w2,
    const float* __restrict__ w3,
    float* __restrict__ av, float* __restrict__ bm, float* __restrict__ w1t)
{
    int b = blockIdx.z;
    const float* A = Stg + (size_t)b * 65536;
    const float* B = Xg + (size_t)b * 65536;
    float* C = XNg + (size_t)b * 65536;
    int q0 = blockIdx.y * 32, r0 = blockIdx.x * 64;
    int tid = threadIdx.x, tx = tid & 15, ty = tid >> 4;

    __shared__ float As[2][16][36];
    __shared__ float Bs[2][16][68];
    float4 ra0, ra1, rb[4];

    auto fetch = [&](int p0) {
        int q1 = q0 + (tid >> 2);
        int pc = p0 + (tid & 3) * 4;
        ra0 = *(const float4*)&A[(size_t)q1 * 256 + pc];
        ra1 = *(const float4*)&A[(size_t)(q1 + 16) * 256 + pc];
        int p1 = p0 + (tid >> 4);
        int rc = r0 + (tid & 15) * 4;
#pragma unroll
        for (int w = 0; w < 4; w++)
            rb[w] = *(const float4*)&B[(size_t)(p1 + 4 * w) * 256 + rc];
    };
    auto store = [&](int buf) {
        int row = tid >> 2, pc = (tid & 3) * 4;
        As[buf][pc + 0][row] = ra0.x; As[buf][pc + 1][row] = ra0.y;
        As[buf][pc + 2][row] = ra0.z; As[buf][pc + 3][row] = ra0.w;
        As[buf][pc + 0][row + 16] = ra1.x; As[buf][pc + 1][row + 16] = ra1.y;
        As[buf][pc + 2][row + 16] = ra1.z; As[buf][pc + 3][row + 16] = ra1.w;
        int p = tid >> 4, rc2 = (tid & 15) * 4;
#pragma unroll
        for (int w = 0; w < 4; w++)
            *(float4*)&Bs[buf][p + 4 * w][rc2] = rb[w];
    };

    float acc[8][4] = {};
    fetch(0); store(0);
    __syncthreads();
    for (int c = 0; c < 16; c++) {
        int cur = c & 1;
        if (c + 1 < 16) fetch((c + 1) * 16);
#pragma unroll
        for (int k = 0; k < 16; k++) {
            float4 a0 = *(const float4*)&As[cur][k][ty * 8];
            float4 a1 = *(const float4*)&As[cur][k][ty * 8 + 4];
            float4 b0 = *(const float4*)&Bs[cur][k][tx * 4];
            float avv[8] = {a0.x, a0.y, a0.z, a0.w, a1.x, a1.y, a1.z, a1.w};
            float bv[4] = {b0.x, b0.y, b0.z, b0.w};
#pragma unroll
            for (int i = 0; i < 8; i++)
#pragma unroll
                for (int j = 0; j < 4; j++) acc[i][j] = fmaf(avv[i], bv[j], acc[i][j]);
        }
        if (c + 1 < 16) store(cur ^ 1);
        __syncthreads();
    }

    float w1v[4], w2v[4], w3v[4];
#pragma unroll
    for (int j = 0; j < 4; j++) {
        int r = r0 + tx * 4 + j;
        w1v[j] = w1[r]; w2v[j] = w2[r]; w3v[j] = w3[r];
    }

#pragma unroll
    for (int i = 0; i < 8; i++) {
        int q = q0 + ty * 8 + i;
        float p1 = 0.f, p2 = 0.f, p3 = 0.f;
#pragma unroll
        for (int j = 0; j < 4; j++) {
            int r = r0 + tx * 4 + j;
            float v = acc[i][j];
            C[(size_t)q * 256 + r] = v;
            p1 = fmaf(v, w1v[j], p1);
            p2 = fmaf(v, w2v[j], p2);
            p3 = fmaf(v, w3v[j], p3);
        }
#pragma unroll
        for (int o = 8; o; o >>= 1) {
            p1 += __shfl_xor_sync(0xffffffffu, p1, o);
            p2 += __shfl_xor_sync(0xffffffffu, p2, o);
            p3 += __shfl_xor_sync(0xffffffffu, p3, o);
        }
        if (tx == 0) {
            int node = (b << 8) + q;
            atomicAdd(&w1t[node], p1);
            atomicAdd(&av[node], p2);
            atomicAdd(&bm[node], p3);
        }
    }
}

// k_w2: U = X@Wr, V = X@Wo + br. Grid (8, ceil(M/32)); x<4 -> Wr/U else Wo/V.
__global__ __launch_bounds__(64) void k_w2(
    const float* __restrict__ X,
    const float* __restrict__ Wr, const float* __restrict__ Wo,
    const float* __restrict__ br,
    float* __restrict__ U, float* __restrict__ V, int M)
{
    int sel = blockIdx.x >> 2;
    int r0 = (blockIdx.x & 3) * 64, q0 = blockIdx.y * 32;
    const float* W = sel ? Wo : Wr;
    float* O = sel ? V : U;
    int tid = threadIdx.x, tx = tid & 15, ty = tid >> 4;

    __shared__ float As[2][16][36];
    __shared__ float Bs[2][16][68];
    float4 ra0, ra1, rb[4];

    auto fetch = [&](int p0) {
        int q1 = q0 + (tid >> 2);
        int pc = p0 + (tid & 3) * 4;
        ra0 = (q1 < M) ? *(const float4*)&X[(size_t)q1 * 256 + pc] : zf4();
        ra1 = (q1 + 16 < M) ? *(const float4*)&X[(size_t)(q1 + 16) * 256 + pc] : zf4();
        int p1 = p0 + (tid >> 4);
        int rc = r0 + (tid & 15) * 4;
#pragma unroll
        for (int w = 0; w < 4; w++)
            rb[w] = *(const float4*)&W[(size_t)(p1 + 4 * w) * 256 + rc];
    };
    auto store = [&](int buf) {
        int row = tid >> 2, pc = (tid & 3) * 4;
        As[buf][pc + 0][row] = ra0.x; As[buf][pc + 1][row] = ra0.y;
        As[buf][pc + 2][row] = ra0.z; As[buf][pc + 3][row] = ra0.w;
        As[buf][pc + 0][row + 16] = ra1.x; As[buf][pc + 1][row + 16] = ra1.y;
        As[buf][pc + 2][row + 16] = ra1.z; As[buf][pc + 3][row + 16] = ra1.w;
        int p = tid >> 4, rc2 = (tid & 15) * 4;
#pragma unroll
        for (int w = 0; w < 4; w++)
            *(float4*)&Bs[buf][p + 4 * w][rc2] = rb[w];
    };

    float acc[8][4] = {};
    fetch(0); store(0);
    __syncthreads();
    for (int c = 0; c < 16; c++) {
        int cur = c & 1;
        if (c + 1 < 16) fetch((c + 1) * 16);
#pragma unroll
        for (int k = 0; k < 16; k++) {
            float4 a0 = *(const float4*)&As[cur][k][ty * 8];
            float4 a1 = *(const float4*)&As[cur][k][ty * 8 + 4];
            float4 b0 = *(const float4*)&Bs[cur][k][tx * 4];
            float avv[8] = {a0.x, a0.y, a0.z, a0.w, a1.x, a1.y, a1.z, a1.w};
            float bv[4] = {b0.x, b0.y, b0.z, b0.w};
#pragma unroll
            for (int i = 0; i < 8; i++)
#pragma unroll
                for (int j = 0; j < 4; j++) acc[i][j] = fmaf(avv[i], bv[j], acc[i][j]);
        }
        if (c + 1 < 16) store(cur ^ 1);
        __syncthreads();
    }

#pragma unroll
    for (int i = 0; i < 8; i++) {
        int q = q0 + ty * 8 + i;
        if (q >= M) continue;
#pragma unroll
        for (int j = 0; j < 4; j++) {
            int r = r0 + tx * 4 + j;
            float v = acc[i][j];
            if (sel) v += br[r];
            O[(size_t)q * 256 + r] = v;
        }
    }
}

// ---------------------------------------------------------------------------
// k_adj: Y[q][r] = relu( (sum_p Aop(p,q) U[p][r]) / max(S[q],1) + V[q][r] )
// PLUS fused column-sum pooling into part[slot][g][r].
// ---------------------------------------------------------------------------
template <int MA>
__global__ __launch_bounds__(64) void k_adj(
    const float* __restrict__ Ag, const float* __restrict__ Ug,
    const float* __restrict__ Vg, const float* __restrict__ Sg,
    float* __restrict__ Yg, float* __restrict__ part, int slot,
    int P, int Q, int ldA, int sA, int sM, int sS)
{
    int b = blockIdx.z;
    const float* A = Ag + (size_t)b * sA;
    const float* U = Ug + (size_t)b * sM;
    const float* V = Vg + (size_t)b * sM;
    const float* S = Sg + (size_t)b * sS;
    float* Y = Yg + (size_t)b * sM;
    int q0 = blockIdx.y * 32, r0 = blockIdx.x * 64;
    int tid = threadIdx.x, tx = tid & 15, ty = tid >> 4;

    __shared__ float As[2][16][36];
    __shared__ float Bs[2][16][68];
    __shared__ float pools[4][64];
    float4 ra0, ra1, rb[4];

    auto fetch = [&](int p0) {
        if (MA == 0) {
            int q1 = q0 + (tid >> 2);
            int pc = p0 + (tid & 3) * 4;
            ra0 = (q1 < Q) ? *(const float4*)&A[(size_t)q1 * ldA + pc] : zf4();
            ra1 = (q1 + 16 < Q) ? *(const float4*)&A[(size_t)(q1 + 16) * ldA + pc] : zf4();
        } else {
            int p1 = p0 + (tid >> 3);
            int qc = q0 + (tid & 7) * 4;
            ra0 = (p1 < P) ? *(const float4*)&A[(size_t)p1 * ldA + qc] : zf4();
            ra1 = (p1 + 8 < P) ? *(const float4*)&A[(size_t)(p1 + 8) * ldA + qc] : zf4();
        }
        int p1 = p0 + (tid >> 4);
        int rc = r0 + (tid & 15) * 4;
#pragma unroll
        for (int w = 0; w < 4; w++)
            rb[w] = (p1 + 4 * w < P) ? *(const float4*)&U[(size_t)(p1 + 4 * w) * 256 + rc] : zf4();
    };
    auto store = [&](int buf) {
        if (MA == 0) {
            int row = tid >> 2, pc = (tid & 3) * 4;
            As[buf][pc + 0][row] = ra0.x; As[buf][pc + 1][row] = ra0.y;
            As[buf][pc + 2][row] = ra0.z; As[buf][pc + 3][row] = ra0.w;
            As[buf][pc + 0][row + 16] = ra1.x; As[buf][pc + 1][row + 16] = ra1.y;
            As[buf][pc + 2][row + 16] = ra1.z; As[buf][pc + 3][row + 16] = ra1.w;
        } else {
            int p = tid >> 3, qc = (tid & 7) * 4;
            *(float4*)&As[buf][p][qc] = ra0;
            *(float4*)&As[buf][p + 8][qc] = ra1;
        }
        int p = tid >> 4, rc2 = (tid & 15) * 4;
#pragma unroll
        for (int w = 0; w < 4; w++)
            *(float4*)&Bs[buf][p + 4 * w][rc2] = rb[w];
    };

    float acc[8][4] = {};
    fetch(0); store(0);
    __syncthreads();
    int nch = (P + 15) >> 4;
    for (int c = 0; c < nch; c++) {
        int cur = c & 1;
        if (c + 1 < nch) fetch((c + 1) * 16);
#pragma unroll
        for (int k = 0; k < 16; k++) {
            float4 a0 = *(const float4*)&As[cur][k][ty * 8];
            float4 a1 = *(const float4*)&As[cur][k][ty * 8 + 4];
            float4 b0 = *(const float4*)&Bs[cur][k][tx * 4];
            float avv[8] = {a0.x, a0.y, a0.z, a0.w, a1.x, a1.y, a1.z, a1.w};
            float bv[4] = {b0.x, b0.y, b0.z, b0.w};
#pragma unroll
            for (int i = 0; i < 8; i++)
#pragma unroll
                for (int j = 0; j < 4; j++) acc[i][j] = fmaf(avv[i], bv[j], acc[i][j]);
        }
        if (c + 1 < nch) store(cur ^ 1);
        __syncthreads();
    }

    float psum[4] = {0.f, 0.f, 0.f, 0.f};
#pragma unroll
    for (int i = 0; i < 8; i++) {
        int q = q0 + ty * 8 + i;
        if (q >= Q) continue;
        float d = fmaxf(S[q], 1.f);
#pragma unroll
        for (int j = 0; j < 4; j++) {
            int r = r0 + tx * 4 + j;
            float v = acc[i][j] / d + V[(size_t)q * 256 + r];
            v = v > 0.f ? v : 0.f;
            Y[(size_t)q * 256 + r] = v;
            psum[j] += v;
        }
    }
#pragma unroll
    for (int j = 0; j < 4; j++) pools[ty][tx * 4 + j] = psum[j];
    __syncthreads();
    float colsum = pools[0][tid] + pools[1][tid] + pools[2][tid] + pools[3][tid];
    atomicAdd(&part[(size_t)(slot * 16 + b) * 256 + r0 + tid], colsum);
}

// ---------------------------------------------------------------------------
extern "C" void kernel_launch(void* const* d_in, const int* in_sizes, int n_in,
                              void* d_out, int out_size)
{
    float* buf = nullptr;
    cudaGetSymbolAddress((void**)&buf, g_buf);

    float* At   = buf + OFF_AT;
    float* St   = buf + OFF_ST;
    float* xa   = buf + OFF_XA;
    float* xb   = buf + OFF_XB;       // reused as M1full
    float* xnew = buf + OFF_XNEW;
    float* Ubuf = buf + OFF_U;
    float* Vbuf = buf + OFF_V2;
    float* Zbuf = buf + OFF_Z;
    float* A2   = buf + OFF_A2;
    float* xsel = buf + OFF_XSEL;
    float* xs2  = buf + OFF_XS2;
    float* xs3  = buf + OFF_XS3;
    float* cnt  = buf + OFF_CNT;
    float* vv   = buf + OFF_V;
    float* av   = buf + OFF_AV;
    float* bm   = buf + OFF_BM;
    float* w1t  = buf + OFF_W1T;
    float* fit  = buf + OFF_FIT;
    float* cnt2 = buf + OFF_CNT2;
    float* wlq  = buf + OFF_WLQ;
    float* part = buf + OFF_PART;
    int*   perm = (int*)(buf + OFF_PERM);

    const int*   x_type   = (const int*)d_in[0];
    const int*   node_dep = (const int*)d_in[1];
    const int*   eidx     = (const int*)d_in[2];
    const float* emb_type = (const float*)d_in[3];
    const float* emb_dep  = (const float*)d_in[4];
    const float* c0_Wr = (const float*)d_in[5];
    const float* c0_br = (const float*)d_in[6];
    const float* c0_Wo = (const float*)d_in[7];
    const float* c1_Wr = (const float*)d_in[8];
    const float* c1_br = (const float*)d_in[9];
    const float* c1_Wo = (const float*)d_in[10];
    const float* c2_Wr = (const float*)d_in[11];
    const float* c2_br = (const float*)d_in[12];
    const float* c2_Wo = (const float*)d_in[13];
    const float* c3_Wr = (const float*)d_in[14];
    const float* c3_br = (const float*)d_in[15];
    const float* c3_Wo = (const float*)d_in[16];
    const float* p_Wlin = (const float*)d_in[17];
    const float* p_blin = (const float*)d_in[18];
    const float* p_Watt = (const float*)d_in[19];
    const float* p_batt = (const float*)d_in[20];
    const float* le_W1 = (const float*)d_in[21];
    const float* le_b1 = (const float*)d_in[22];
    const float* le_W2 = (const float*)d_in[23];
    const float* le_W3 = (const float*)d_in[24];
    const float* le_b3 = (const float*)d_in[25];
    const float* lin1_W = (const float*)d_in[26];
    const float* lin1_b = (const float*)d_in[27];
    const float* pred_W = (const float*)d_in[28];
    const float* pred_b = (const float*)d_in[29];

    int E = in_sizes[2] / 2;
    const int* src = eidx;
    const int* dst = eidx + E;

    dim3 gW(8, 128);               // M=4096 / 32
    dim3 gWK(8, 103);              // M=3280
    dim3 gAdj(4, 8, BB);           // Q=256 / 32
    dim3 gAdjK(4, 7, BB);          // Q=205
    dim3 gFull(4, 8, BB);          // 256x256 per-graph GEMM

    // ---- prologue (default stream) ----
    cudaMemsetAsync(At, 0, (size_t)BB * 65536 * sizeof(float), 0);
    cudaMemsetAsync(cnt, 0, NN * sizeof(float), 0);
    cudaMemsetAsync(av, 0, 3 * NN * sizeof(float), 0);    // av/bm/w1t
    cudaMemsetAsync(cnt2, 0, 4096 * sizeof(float), 0);
    cudaMemsetAsync(part, 0, 4 * BB * 256 * sizeof(float), 0);
    k_embed<<<NN, 256>>>(x_type, node_dep, emb_type, emb_dep, xa);

    // FORK 1: side runs wlq + k_w2-L0 (needs only xa); main builds adjacency.
    cudaEventRecord(g_ev0, 0);
    cudaStreamWaitEvent(g_s2, g_ev0, 0);
    k_wlq<<<1, 256, 0, g_s2>>>(p_Wlin, p_blin, p_Watt, p_batt, wlq);
    k_w2<<<gW, 64, 0, g_s2>>>(xa, c0_Wr, c0_Wo, c0_br, Ubuf, Vbuf, NN);
    cudaEventRecord(g_ev1, g_s2);

    k_buildA<<<(E + 255) / 256, 256>>>(src, dst, At, cnt, E);

    cudaStreamWaitEvent(0, g_ev1, 0);   // join
    k_adj<0><<<gAdj, 64>>>(At, Ubuf, Vbuf, cnt, xb, part, 0,
                           256, 256, 256, 65536, 65536, 256);

    // layer 1 (serial)
    k_w2<<<gW, 64>>>(xb, c1_Wr, c1_Wo, c1_br, Ubuf, Vbuf, NN);
    k_adj<0><<<gAdj, 64>>>(At, Ubuf, Vbuf, cnt, xa, part, 1,
                           256, 256, 256, 65536, 65536, 256);

    // ASAP attention
    k_diagv<<<BB + NN / 8, 256>>>(At, p_Watt, xa, vv);
    k_att<<<NN, 256>>>(At, xa, vv, wlq, St);

    // FORK 2: side computes M1full = A@S (into xb) then Z = S^T @ M1full —
    // independent of topk; main runs xnew -> fit -> topk.
    cudaEventRecord(g_ev2, 0);
    cudaStreamWaitEvent(g_s2, g_ev2, 0);
    bgemm<1, 1><<<gFull, 64, 0, g_s2>>>(At, St, xb, 256, 256, 256, 256, 256, 256,
                                        65536, 65536, 65536);
    bgemm<0, 0><<<gFull, 64, 0, g_s2>>>(St, xb, Zbuf, 256, 256, 256, 256, 256, 256,
                                        65536, 65536, 65536);

    k_xnew<<<gFull, 64>>>(St, xa, xnew, le_W1, le_W2, le_W3, av, bm, w1t);
    k_fit<<<NN / 8, 256>>>(At, av, bm, w1t, cnt, le_b1, le_b3, fit);
    k_topk<<<BB, 256>>>(fit, perm);
    cudaEventRecord(g_evT, 0);

    // side: gather A2 = Z[perm,perm] (diag := 1) + cnt2 once perm is ready
    cudaStreamWaitEvent(g_s2, g_evT, 0);
    k_a2<<<KTOT, 256, 0, g_s2>>>(perm, Zbuf, A2, cnt2);
    cudaEventRecord(g_ev3, g_s2);

    // main: select + layer-2 weight GEMM meanwhile
    k_sel<<<KTOT, 256>>>(perm, xnew, fit, xsel);
    k_w2<<<gWK, 64>>>(xsel, c2_Wr, c2_Wo, c2_br, Ubuf, Vbuf, KTOT);

    cudaStreamWaitEvent(0, g_ev3, 0);   // join (A2 + cnt2 ready)
    k_adj<1><<<gAdjK, 64>>>(A2, Ubuf, Vbuf, cnt2, xs2, part, 2,
                            KPER, KPER, LD2, LD2 * LD2, KPER * 256, KPER);

    // layer 3 (serial)
    k_w2<<<gWK, 64>>>(xs2, c3_Wr, c3_Wo, c3_br, Ubuf, Vbuf, KTOT);
    k_adj<1><<<gAdjK, 64>>>(A2, Ubuf, Vbuf, cnt2, xs3, part, 3,
                            KPER, KPER, LD2, LD2 * LD2, KPER * 256, KPER);

    k_head<<<BB, 256>>>(part, lin1_W, lin1_b, pred_W, pred_b, (float*)d_out);
}

// round 17
// speedup vs baseline: 1.0359x; 1.0128x over previous
#include <cuda_runtime.h>
#include <math.h>
#include <stdint.h>

#define NN    4096
#define BB    16
#define KPER  205
#define KTOT  3280
#define LD2   208

// ---------------------------------------------------------------------------
// Scratch. cnt..part contiguous -> single memset; wlq outside zeroed span.
// ---------------------------------------------------------------------------
constexpr size_t OFF_AT   = 0;
constexpr size_t OFF_ST   = OFF_AT   + 1048576;
constexpr size_t OFF_XA   = OFF_ST   + 1048576;
constexpr size_t OFF_XB   = OFF_XA   + 1048576;   // reused as M1full
constexpr size_t OFF_XNEW = OFF_XB   + 1048576;
constexpr size_t OFF_U    = OFF_XNEW + 1048576;
constexpr size_t OFF_V2   = OFF_U    + 1048576;
constexpr size_t OFF_Z    = OFF_V2   + 1048576;
constexpr size_t OFF_A2   = OFF_Z    + 1703936;
constexpr size_t OFF_XSEL = OFF_A2   + 692224;
constexpr size_t OFF_XS2  = OFF_XSEL + 839680;
constexpr size_t OFF_XS3  = OFF_XS2  + 839680;
// ---- zeroed span starts here ----
constexpr size_t OFF_CNT  = OFF_XS3  + 839680;
constexpr size_t OFF_V    = OFF_CNT  + 4096;
constexpr size_t OFF_AV   = OFF_V    + 4096;
constexpr size_t OFF_BM   = OFF_AV   + 4096;
constexpr size_t OFF_W1T  = OFF_BM   + 4096;
constexpr size_t OFF_FIT  = OFF_W1T  + 4096;
constexpr size_t OFF_CNT2 = OFF_FIT  + 4096;
constexpr size_t OFF_PART = OFF_CNT2 + 4096;
constexpr size_t ZERO_SPAN = 7 * 4096 + 16384;     // cnt..part inclusive
// ---- zeroed span ends here ----
constexpr size_t OFF_WLQ  = OFF_PART + 16384;
constexpr size_t OFF_PERM = OFF_WLQ  + 512;
constexpr size_t BUF_TOT  = OFF_PERM + 4096;

__device__ __align__(256) float g_buf[BUF_TOT];

__device__ __forceinline__ float4 zf4() { return make_float4(0.f, 0.f, 0.f, 0.f); }

// ---------------------------------------------------------------------------
// Side stream + events (capture-legal fork/join).
// ---------------------------------------------------------------------------
static cudaStream_t g_s2;
static cudaEvent_t  g_ev0, g_ev1, g_ev2, g_ev3, g_evT;
namespace {
struct SideStreamInit {
    SideStreamInit() {
        cudaStreamCreateWithFlags(&g_s2, cudaStreamNonBlocking);
        cudaEventCreateWithFlags(&g_ev0, cudaEventDisableTiming);
        cudaEventCreateWithFlags(&g_ev1, cudaEventDisableTiming);
        cudaEventCreateWithFlags(&g_ev2, cudaEventDisableTiming);
        cudaEventCreateWithFlags(&g_ev3, cudaEventDisableTiming);
        cudaEventCreateWithFlags(&g_evT, cudaEventDisableTiming);
    }
};
SideStreamInit g_side_stream_init;
}

// ---------------------------------------------------------------------------
// Small kernels
// ---------------------------------------------------------------------------
__global__ void k_embed(const int* __restrict__ xt, const int* __restrict__ nd,
                        const float* __restrict__ et, const float* __restrict__ ed,
                        float* __restrict__ out)
{
    int i = blockIdx.x, t = threadIdx.x;
    out[i * 256 + t] = et[xt[i] * 256 + t] + ed[nd[i] * 256 + t];
}

__global__ void k_buildA(const int* __restrict__ src, const int* __restrict__ dst,
                         float* __restrict__ At, float* __restrict__ cnt, int E)
{
    int e = blockIdx.x * blockDim.x + threadIdx.x;
    if (e >= E) return;
    int s = src[e], d = dst[e];
    int g = s >> 8, r = s & 255, c = d & 255;
    atomicAdd(&At[((size_t)g * 256 + c) * 256 + r], 1.0f);
    atomicAdd(&cnt[(g << 8) + c], 1.0f);
}

__global__ void k_wlq(const float* __restrict__ Wlin, const float* __restrict__ blin,
                      const float* __restrict__ watt, const float* __restrict__ batt,
                      float* __restrict__ wlq)
{
    int t = threadIdx.x;
    float s = 0.f;
    for (int j = 0; j < 256; j++) s += Wlin[t * 256 + j] * watt[j];
    wlq[t] = s;
    if (t == 0) {
        float c = 0.f;
        for (int j = 0; j < 256; j++) c += blin[j] * watt[j];
        wlq[256] = c + batt[0];
    }
}

// add self-loop diagonal (16 blocks only)
__global__ void k_diag(float* __restrict__ At)
{
    int g = blockIdx.x, t = threadIdx.x;
    At[((size_t)g * 256 + t) * 256 + t] += 1.0f;
}

__global__ void k_att(const float* __restrict__ At, const float* __restrict__ x,
                      const float* __restrict__ v, const float* __restrict__ wlq,
                      float* __restrict__ St)
{
    int col = blockIdx.x, g = col >> 8, t = threadIdx.x;
    __shared__ int list[256];
    __shared__ int nnb;
    __shared__ float red[256];
    if (!t) nnb = 0;
    __syncthreads();
    float av = At[(size_t)col * 256 + t];
    if (av > 0.f) { int p = atomicAdd(&nnb, 1); list[p] = t; }
    __syncthreads();
    int n = nnb;
    const float* xg = x + ((size_t)(g << 8)) * 256;
    float m = -1e30f;
    int i = 0;
    for (; i + 4 <= n; i += 4) {
        float m0 = xg[list[i + 0] * 256 + t];
        float m1 = xg[list[i + 1] * 256 + t];
        float m2 = xg[list[i + 2] * 256 + t];
        float m3 = xg[list[i + 3] * 256 + t];
        m = fmaxf(m, fmaxf(fmaxf(m0, m1), fmaxf(m2, m3)));
    }
    for (; i < n; i++) m = fmaxf(m, xg[list[i] * 256 + t]);
    red[t] = m * wlq[t];
    __syncthreads();
    for (int o = 128; o; o >>= 1) { if (t < o) red[t] += red[t + o]; __syncthreads(); }
    float su = red[0] + wlq[256];
    __syncthreads();
    float vm = -1e30f;
    const float* vg = v + (g << 8);
    for (int j = t; j < n; j += 256) vm = fmaxf(vm, vg[list[j]]);
    red[t] = vm;
    __syncthreads();
    for (int o = 128; o; o >>= 1) { if (t < o) red[t] = fmaxf(red[t], red[t + o]); __syncthreads(); }
    float vmax = red[0];
    __syncthreads();
    float s = su + v[(g << 8) + t];
    s = s > 0.f ? s : 0.2f * s;
    float sm = su + vmax;
    sm = sm > 0.f ? sm : 0.2f * sm;
    float e = av > 0.f ? av * expf(s - sm) : 0.f;
    red[t] = e;
    __syncthreads();
    for (int o = 128; o; o >>= 1) { if (t < o) red[t] += red[t + o]; __syncthreads(); }
    St[(size_t)col * 256 + t] = e / red[0];
}

__global__ void k_fit(const float* __restrict__ At, const float* __restrict__ av,
                      const float* __restrict__ bm, const float* __restrict__ w1t,
                      const float* __restrict__ cnt, const float* __restrict__ b1,
                      const float* __restrict__ b3, float* __restrict__ fit)
{
    int node = (blockIdx.x * 256 + threadIdx.x) >> 5;
    int lane = threadIdx.x & 31;
    int g = node >> 8;
    const float* row = At + (size_t)node * 256;
    const float* ag = av + (g << 8);
    float s = 0.f;
    for (int j = lane; j < 256; j += 32) s += row[j] * ag[j];
    for (int o = 16; o; o >>= 1) s += __shfl_xor_sync(0xffffffffu, s, o);
    if (!lane) {
        float f = s - (cnt[node] + 1.f) * (bm[node] + b3[0]) + w1t[node] + b1[0];
        fit[node] = 1.f / (1.f + expf(-f));
    }
}

__global__ void k_topk(const float* __restrict__ fit, int* __restrict__ perm)
{
    int g = blockIdx.x, i = threadIdx.x;
    __shared__ float f[256];
    f[i] = fit[g * 256 + i];
    __syncthreads();
    float fi = f[i];
    int r = 0;
    for (int j = 0; j < 256; j++) {
        float fj = f[j];
        r += (fj > fi) || (fj == fi && j < i);
    }
    if (r < KPER) perm[g * KPER + r] = i;
}

__global__ void k_sel(const int* __restrict__ perm, const float* __restrict__ xnew,
                      const float* __restrict__ fit, float* __restrict__ xsel)
{
    int k = blockIdx.x, t = threadIdx.x;
    int g = k / KPER;
    int gi = (g << 8) + perm[k];
    xsel[(size_t)k * 256 + t] = xnew[(size_t)gi * 256 + t] * fit[gi];
}

// A2[i][j] = (i==j) ? 1 : Z[perm_i][perm_j]; cnt2[j] += (val != 0)
__global__ void k_a2(const int* __restrict__ perm, const float* __restrict__ Z,
                     float* __restrict__ A2, float* __restrict__ cnt2)
{
    int k = blockIdx.x;
    int g = k / KPER, i = k - g * KPER;
    int t = threadIdx.x;
    if (t >= KPER) return;
    const int* pg = perm + g * KPER;
    const float* Zr = Z + (size_t)g * 65536 + (size_t)pg[i] * 256;
    float v = (t == i) ? 1.f : Zr[pg[t]];
    A2[(size_t)g * LD2 * LD2 + (size_t)i * LD2 + t] = v;
    if (v != 0.f) atomicAdd(&cnt2[g * KPER + t], 1.f);
}

__global__ void k_head(const float* __restrict__ part, const float* __restrict__ W1,
                       const float* __restrict__ b1, const float* __restrict__ W2,
                       const float* __restrict__ b2, float* __restrict__ out)
{
    int g = blockIdx.x, t = threadIdx.x;
    __shared__ float hin[1024];
    __shared__ float h2[256];
    for (int k = t; k < 1024; k += 256) {
        int slot = k >> 8, feat = k & 255;
        float s = part[(size_t)(slot * 16 + g) * 256 + feat];
        hin[k] = s / (slot < 2 ? 256.f : (float)KPER);
    }
    __syncthreads();
    float s = 0.f;
    for (int k = 0; k < 1024; k++) s += hin[k] * W1[k * 256 + t];
    s += b1[t];
    h2[t] = s > 0.f ? s : 0.f;
    __syncthreads();
    if (t < 128) {
        float o = 0.f;
        for (int k = 0; k < 256; k++) o += h2[k] * W2[k * 128 + t];
        out[g * 128 + t] = o + b2[t];
    }
}

// ---------------------------------------------------------------------------
// GEMM core (proven config): 32(q) x 64(r) x 16 tile, 64 threads, 8x4 micro.
// ---------------------------------------------------------------------------
template <int MA, int MB>
__global__ __launch_bounds__(64) void bgemm(
    const float* __restrict__ Ag, const float* __restrict__ Bg,
    float* __restrict__ Cg,
    int P, int Q, int R, int ldA, int ldB, int ldC,
    int sA, int sB, int sC)
{
    int b = blockIdx.z;
    const float* A = Ag + (size_t)b * sA;
    const float* B = Bg + (size_t)b * sB;
    float* C = Cg + (size_t)b * sC;
    int q0 = blockIdx.y * 32, r0 = blockIdx.x * 64;
    int tid = threadIdx.x, tx = tid & 15, ty = tid >> 4;

    __shared__ float As[2][16][36];
    __shared__ float Bs[2][16][68];
    float4 ra0, ra1, rb[4];

    auto fetch = [&](int p0) {
        if (MA == 0) {
            int q1 = q0 + (tid >> 2);
            int pc = p0 + (tid & 3) * 4;
            ra0 = (q1 < Q) ? *(const float4*)&A[(size_t)q1 * ldA + pc] : zf4();
            ra1 = (q1 + 16 < Q) ? *(const float4*)&A[(size_t)(q1 + 16) * ldA + pc] : zf4();
        } else {
            int p1 = p0 + (tid >> 3);
            int qc = q0 + (tid & 7) * 4;
            ra0 = (p1 < P) ? *(const float4*)&A[(size_t)p1 * ldA + qc] : zf4();
            ra1 = (p1 + 8 < P) ? *(const float4*)&A[(size_t)(p1 + 8) * ldA + qc] : zf4();
        }
        if (MB == 0) {
            int p1 = p0 + (tid >> 4);
            int rc = r0 + (tid & 15) * 4;
#pragma unroll
            for (int w = 0; w < 4; w++)
                rb[w] = (p1 + 4 * w < P) ? *(const float4*)&B[(size_t)(p1 + 4 * w) * ldB + rc] : zf4();
        } else {
            int r1 = r0 + (tid >> 2);
            int pc = p0 + (tid & 3) * 4;
#pragma unroll
            for (int w = 0; w < 4; w++)
                rb[w] = (r1 + 16 * w < R) ? *(const float4*)&B[(size_t)(r1 + 16 * w) * ldB + pc] : zf4();
        }
    };
    auto store = [&](int buf) {
        if (MA == 0) {
            int row = tid >> 2, pc = (tid & 3) * 4;
            As[buf][pc + 0][row] = ra0.x; As[buf][pc + 1][row] = ra0.y;
            As[buf][pc + 2][row] = ra0.z; As[buf][pc + 3][row] = ra0.w;
            As[buf][pc + 0][row + 16] = ra1.x; As[buf][pc + 1][row + 16] = ra1.y;
            As[buf][pc + 2][row + 16] = ra1.z; As[buf][pc + 3][row + 16] = ra1.w;
        } else {
            int p = tid >> 3, qc = (tid & 7) * 4;
            *(float4*)&As[buf][p][qc] = ra0;
            *(float4*)&As[buf][p + 8][qc] = ra1;
        }
        if (MB == 0) {
            int p = tid >> 4, rc = (tid & 15) * 4;
#pragma unroll
            for (int w = 0; w < 4; w++)
                *(float4*)&Bs[buf][p + 4 * w][rc] = rb[w];
        } else {
            int row = tid >> 2, pc = (tid & 3) * 4;
#pragma unroll
            for (int w = 0; w < 4; w++) {
                Bs[buf][pc + 0][row + 16 * w] = rb[w].x;
                Bs[buf][pc + 1][row + 16 * w] = rb[w].y;
                Bs[buf][pc + 2][row + 16 * w] = rb[w].z;
                Bs[buf][pc + 3][row + 16 * w] = rb[w].w;
            }
        }
    };

    float acc[8][4] = {};
    fetch(0); store(0);
    __syncthreads();
    int nch = (P + 15) >> 4;
    for (int c = 0; c < nch; c++) {
        int cur = c & 1;
        if (c + 1 < nch) fetch((c + 1) * 16);
#pragma unroll
        for (int k = 0; k < 16; k++) {
            float4 a0 = *(const float4*)&As[cur][k][ty * 8];
            float4 a1 = *(const float4*)&As[cur][k][ty * 8 + 4];
            float4 b0 = *(const float4*)&Bs[cur][k][tx * 4];
            float avv[8] = {a0.x, a0.y, a0.z, a0.w, a1.x, a1.y, a1.z, a1.w};
            float bv[4] = {b0.x, b0.y, b0.z, b0.w};
#pragma unroll
            for (int i = 0; i < 8; i++)
#pragma unroll
                for (int j = 0; j < 4; j++) acc[i][j] = fmaf(avv[i], bv[j], acc[i][j]);
        }
        if (c + 1 < nch) store(cur ^ 1);
        __syncthreads();
    }

#pragma unroll
    for (int i = 0; i < 8; i++) {
        int q = q0 + ty * 8 + i;
        if (q >= Q) continue;
#pragma unroll
        for (int j = 0; j < 4; j++) {
            int r = r0 + tx * 4 + j;
            if (r >= R) continue;
            C[(size_t)q * ldC + r] = acc[i][j];
        }
    }
}

// ---------------------------------------------------------------------------
// k_xnew: xnew = St @ x + fused le-dots into av/bm/w1t.
// ---------------------------------------------------------------------------
__global__ __launch_bounds__(64) void k_xnew(
    const float* __restrict__ Stg, const float* __restrict__ Xg,
    float* __restrict__ XNg,
    const float* __restrict__ w1, const float* __restrict__ w2,
    const float* __restrict__ w3,
    float* __restrict__ av, float* __restrict__ bm, float* __restrict__ w1t)
{
    int b = blockIdx.z;
    const float* A = Stg + (size_t)b * 65536;
    const float* B = Xg + (size_t)b * 65536;
    float* C = XNg + (size_t)b * 65536;
    int q0 = blockIdx.y * 32, r0 = blockIdx.x * 64;
    int tid = threadIdx.x, tx = tid & 15, ty = tid >> 4;

    __shared__ float As[2][16][36];
    __shared__ float Bs[2][16][68];
    float4 ra0, ra1, rb[4];

    auto fetch = [&](int p0) {
        int q1 = q0 + (tid >> 2);
        int pc = p0 + (tid & 3) * 4;
        ra0 = *(const float4*)&A[(size_t)q1 * 256 + pc];
        ra1 = *(const float4*)&A[(size_t)(q1 + 16) * 256 + pc];
        int p1 = p0 + (tid >> 4);
        int rc = r0 + (tid & 15) * 4;
#pragma unroll
        for (int w = 0; w < 4; w++)
            rb[w] = *(const float4*)&B[(size_t)(p1 + 4 * w) * 256 + rc];
    };
    auto store = [&](int buf) {
        int row = tid >> 2, pc = (tid & 3) * 4;
        As[buf][pc + 0][row] = ra0.x; As[buf][pc + 1][row] = ra0.y;
        As[buf][pc + 2][row] = ra0.z; As[buf][pc + 3][row] = ra0.w;
        As[buf][pc + 0][row + 16] = ra1.x; As[buf][pc + 1][row + 16] = ra1.y;
        As[buf][pc + 2][row + 16] = ra1.z; As[buf][pc + 3][row + 16] = ra1.w;
        int p = tid >> 4, rc2 = (tid & 15) * 4;
#pragma unroll
        for (int w = 0; w < 4; w++)
            *(float4*)&Bs[buf][p + 4 * w][rc2] = rb[w];
    };

    float acc[8][4] = {};
    fetch(0); store(0);
    __syncthreads();
    for (int c = 0; c < 16; c++) {
        int cur = c & 1;
        if (c + 1 < 16) fetch((c + 1) * 16);
#pragma unroll
        for (int k = 0; k < 16; k++) {
            float4 a0 = *(const float4*)&As[cur][k][ty * 8];
            float4 a1 = *(const float4*)&As[cur][k][ty * 8 + 4];
            float4 b0 = *(const float4*)&Bs[cur][k][tx * 4];
            float avv[8] = {a0.x, a0.y, a0.z, a0.w, a1.x, a1.y, a1.z, a1.w};
            float bv[4] = {b0.x, b0.y, b0.z, b0.w};
#pragma unroll
            for (int i = 0; i < 8; i++)
#pragma unroll
                for (int j = 0; j < 4; j++) acc[i][j] = fmaf(avv[i], bv[j], acc[i][j]);
        }
        if (c + 1 < 16) store(cur ^ 1);
        __syncthreads();
    }

    float w1v[4], w2v[4], w3v[4];
#pragma unroll
    for (int j = 0; j < 4; j++) {
        int r = r0 + tx * 4 + j;
        w1v[j] = w1[r]; w2v[j] = w2[r]; w3v[j] = w3[r];
    }

#pragma unroll
    for (int i = 0; i < 8; i++) {
        int q = q0 + ty * 8 + i;
        float p1 = 0.f, p2 = 0.f, p3 = 0.f;
#pragma unroll
        for (int j = 0; j < 4; j++) {
            int r = r0 + tx * 4 + j;
            float v = acc[i][j];
            C[(size_t)q * 256 + r] = v;
            p1 = fmaf(v, w1v[j], p1);
            p2 = fmaf(v, w2v[j], p2);
            p3 = fmaf(v, w3v[j], p3);
        }
#pragma unroll
        for (int o = 8; o; o >>= 1) {
            p1 += __shfl_xor_sync(0xffffffffu, p1, o);
            p2 += __shfl_xor_sync(0xffffffffu, p2, o);
            p3 += __shfl_xor_sync(0xffffffffu, p3, o);
        }
        if (tx == 0) {
            int node = (b << 8) + q;
            atomicAdd(&w1t[node], p1);
            atomicAdd(&av[node], p2);
            atomicAdd(&bm[node], p3);
        }
    }
}

// k_w2: U = X@Wr, V = X@Wo + br. Grid (8, ceil(M/32)); x<4 -> Wr/U else Wo/V.
__global__ __launch_bounds__(64) void k_w2(
    const float* __restrict__ X,
    const float* __restrict__ Wr, const float* __restrict__ Wo,
    const float* __restrict__ br,
    float* __restrict__ U, float* __restrict__ V, int M)
{
    int sel = blockIdx.x >> 2;
    int r0 = (blockIdx.x & 3) * 64, q0 = blockIdx.y * 32;
    const float* W = sel ? Wo : Wr;
    float* O = sel ? V : U;
    int tid = threadIdx.x, tx = tid & 15, ty = tid >> 4;

    __shared__ float As[2][16][36];
    __shared__ float Bs[2][16][68];
    float4 ra0, ra1, rb[4];

    auto fetch = [&](int p0) {
        int q1 = q0 + (tid >> 2);
        int pc = p0 + (tid & 3) * 4;
        ra0 = (q1 < M) ? *(const float4*)&X[(size_t)q1 * 256 + pc] : zf4();
        ra1 = (q1 + 16 < M) ? *(const float4*)&X[(size_t)(q1 + 16) * 256 + pc] : zf4();
        int p1 = p0 + (tid >> 4);
        int rc = r0 + (tid & 15) * 4;
#pragma unroll
        for (int w = 0; w < 4; w++)
            rb[w] = *(const float4*)&W[(size_t)(p1 + 4 * w) * 256 + rc];
    };
    auto store = [&](int buf) {
        int row = tid >> 2, pc = (tid & 3) * 4;
        As[buf][pc + 0][row] = ra0.x; As[buf][pc + 1][row] = ra0.y;
        As[buf][pc + 2][row] = ra0.z; As[buf][pc + 3][row] = ra0.w;
        As[buf][pc + 0][row + 16] = ra1.x; As[buf][pc + 1][row + 16] = ra1.y;
        As[buf][pc + 2][row + 16] = ra1.z; As[buf][pc + 3][row + 16] = ra1.w;
        int p = tid >> 4, rc2 = (tid & 15) * 4;
#pragma unroll
        for (int w = 0; w < 4; w++)
            *(float4*)&Bs[buf][p + 4 * w][rc2] = rb[w];
    };

    float acc[8][4] = {};
    fetch(0); store(0);
    __syncthreads();
    for (int c = 0; c < 16; c++) {
        int cur = c & 1;
        if (c + 1 < 16) fetch((c + 1) * 16);
#pragma unroll
        for (int k = 0; k < 16; k++) {
            float4 a0 = *(const float4*)&As[cur][k][ty * 8];
            float4 a1 = *(const float4*)&As[cur][k][ty * 8 + 4];
            float4 b0 = *(const float4*)&Bs[cur][k][tx * 4];
            float avv[8] = {a0.x, a0.y, a0.z, a0.w, a1.x, a1.y, a1.z, a1.w};
            float bv[4] = {b0.x, b0.y, b0.z, b0.w};
#pragma unroll
            for (int i = 0; i < 8; i++)
#pragma unroll
                for (int j = 0; j < 4; j++) acc[i][j] = fmaf(avv[i], bv[j], acc[i][j]);
        }
        if (c + 1 < 16) store(cur ^ 1);
        __syncthreads();
    }

#pragma unroll
    for (int i = 0; i < 8; i++) {
        int q = q0 + ty * 8 + i;
        if (q >= M) continue;
#pragma unroll
        for (int j = 0; j < 4; j++) {
            int r = r0 + tx * 4 + j;
            float v = acc[i][j];
            if (sel) v += br[r];
            O[(size_t)q * 256 + r] = v;
        }
    }
}

// ---------------------------------------------------------------------------
// k_adj: Y = relu(diag(1/max(S,1)) A^T U + V), fused pooling into part, and
// OPTIONAL fused v = Y @ vw (vw = watt[256:512]) into vout (layer 1 only).
// ---------------------------------------------------------------------------
template <int MA>
__global__ __launch_bounds__(64) void k_adj(
    const float* __restrict__ Ag, const float* __restrict__ Ug,
    const float* __restrict__ Vg, const float* __restrict__ Sg,
    float* __restrict__ Yg, float* __restrict__ part, int slot,
    const float* __restrict__ vw, float* __restrict__ vout,
    int P, int Q, int ldA, int sA, int sM, int sS)
{
    int b = blockIdx.z;
    const float* A = Ag + (size_t)b * sA;
    const float* U = Ug + (size_t)b * sM;
    const float* V = Vg + (size_t)b * sM;
    const float* S = Sg + (size_t)b * sS;
    float* Y = Yg + (size_t)b * sM;
    int q0 = blockIdx.y * 32, r0 = blockIdx.x * 64;
    int tid = threadIdx.x, tx = tid & 15, ty = tid >> 4;

    __shared__ float As[2][16][36];
    __shared__ float Bs[2][16][68];
    __shared__ float pools[4][64];
    float4 ra0, ra1, rb[4];

    auto fetch = [&](int p0) {
        if (MA == 0) {
            int q1 = q0 + (tid >> 2);
            int pc = p0 + (tid & 3) * 4;
            ra0 = (q1 < Q) ? *(const float4*)&A[(size_t)q1 * ldA + pc] : zf4();
            ra1 = (q1 + 16 < Q) ? *(const float4*)&A[(size_t)(q1 + 16) * ldA + pc] : zf4();
        } else {
            int p1 = p0 + (tid >> 3);
            int qc = q0 + (tid & 7) * 4;
            ra0 = (p1 < P) ? *(const float4*)&A[(size_t)p1 * ldA + qc] : zf4();
            ra1 = (p1 + 8 < P) ? *(const float4*)&A[(size_t)(p1 + 8) * ldA + qc] : zf4();
        }
        int p1 = p0 + (tid >> 4);
        int rc = r0 + (tid & 15) * 4;
#pragma unroll
        for (int w = 0; w < 4; w++)
            rb[w] = (p1 + 4 * w < P) ? *(const float4*)&U[(size_t)(p1 + 4 * w) * 256 + rc] : zf4();
    };
    auto store = [&](int buf) {
        if (MA == 0) {
            int row = tid >> 2, pc = (tid & 3) * 4;
            As[buf][pc + 0][row] = ra0.x; As[buf][pc + 1][row] = ra0.y;
            As[buf][pc + 2][row] = ra0.z; As[buf][pc + 3][row] = ra0.w;
            As[buf][pc + 0][row + 16] = ra1.x; As[buf][pc + 1][row + 16] = ra1.y;
            As[buf][pc + 2][row + 16] = ra1.z; As[buf][pc + 3][row + 16] = ra1.w;
        } else {
            int p = tid >> 3, qc = (tid & 7) * 4;
            *(float4*)&As[buf][p][qc] = ra0;
            *(float4*)&As[buf][p + 8][qc] = ra1;
        }
        int p = tid >> 4, rc2 = (tid & 15) * 4;
#pragma unroll
        for (int w = 0; w < 4; w++)
            *(float4*)&Bs[buf][p + 4 * w][rc2] = rb[w];
    };

    float acc[8][4] = {};
    fetch(0); store(0);
    __syncthreads();
    int nch = (P + 15) >> 4;
    for (int c = 0; c < nch; c++) {
        int cur = c & 1;
        if (c + 1 < nch) fetch((c + 1) * 16);
#pragma unroll
        for (int k = 0; k < 16; k++) {
            float4 a0 = *(const float4*)&As[cur][k][ty * 8];
            float4 a1 = *(const float4*)&As[cur][k][ty * 8 + 4];
            float4 b0 = *(const float4*)&Bs[cur][k][tx * 4];
            float avv[8] = {a0.x, a0.y, a0.z, a0.w, a1.x, a1.y, a1.z, a1.w};
            float bv[4] = {b0.x, b0.y, b0.z, b0.w};
#pragma unroll
            for (int i = 0; i < 8; i++)
#pragma unroll
                for (int j = 0; j < 4; j++) acc[i][j] = fmaf(avv[i], bv[j], acc[i][j]);
        }
        if (c + 1 < nch) store(cur ^ 1);
        __syncthreads();
    }

    float vwv[4] = {0.f, 0.f, 0.f, 0.f};
    if (vw) {
#pragma unroll
        for (int j = 0; j < 4; j++) vwv[j] = vw[r0 + tx * 4 + j];
    }

    float psum[4] = {0.f, 0.f, 0.f, 0.f};
#pragma unroll
    for (int i = 0; i < 8; i++) {
        int q = q0 + ty * 8 + i;
        if (q >= Q) continue;
        float d = fmaxf(S[q], 1.f);
        float pv = 0.f;
#pragma unroll
        for (int j = 0; j < 4; j++) {
            int r = r0 + tx * 4 + j;
            float v = acc[i][j] / d + V[(size_t)q * 256 + r];
            v = v > 0.f ? v : 0.f;
            Y[(size_t)q * 256 + r] = v;
            psum[j] += v;
            pv = fmaf(v, vwv[j], pv);
        }
        if (vw) {
#pragma unroll
            for (int o = 8; o; o >>= 1)
                pv += __shfl_xor_sync(0xffffffffu, pv, o);
            if (tx == 0) atomicAdd(&vout[(b << 8) + q], pv);
        }
    }
#pragma unroll
    for (int j = 0; j < 4; j++) pools[ty][tx * 4 + j] = psum[j];
    __syncthreads();
    float colsum = pools[0][tid] + pools[1][tid] + pools[2][tid] + pools[3][tid];
    atomicAdd(&part[(size_t)(slot * 16 + b) * 256 + r0 + tid], colsum);
}

// ---------------------------------------------------------------------------
extern "C" void kernel_launch(void* const* d_in, const int* in_sizes, int n_in,
                              void* d_out, int out_size)
{
    float* buf = nullptr;
    cudaGetSymbolAddress((void**)&buf, g_buf);

    float* At   = buf + OFF_AT;
    float* St   = buf + OFF_ST;
    float* xa   = buf + OFF_XA;
    float* xb   = buf + OFF_XB;
    float* xnew = buf + OFF_XNEW;
    float* Ubuf = buf + OFF_U;
    float* Vbuf = buf + OFF_V2;
    float* Zbuf = buf + OFF_Z;
    float* A2   = buf + OFF_A2;
    float* xsel = buf + OFF_XSEL;
    float* xs2  = buf + OFF_XS2;
    float* xs3  = buf + OFF_XS3;
    float* cnt  = buf + OFF_CNT;
    float* vv   = buf + OFF_V;
    float* av   = buf + OFF_AV;
    float* bm   = buf + OFF_BM;
    float* w1t  = buf + OFF_W1T;
    float* fit  = buf + OFF_FIT;
    float* cnt2 = buf + OFF_CNT2;
    float* part = buf + OFF_PART;
    float* wlq  = buf + OFF_WLQ;
    int*   perm = (int*)(buf + OFF_PERM);

    const int*   x_type   = (const int*)d_in[0];
    const int*   node_dep = (const int*)d_in[1];
    const int*   eidx     = (const int*)d_in[2];
    const float* emb_type = (const float*)d_in[3];
    const float* emb_dep  = (const float*)d_in[4];
    const float* c0_Wr = (const float*)d_in[5];
    const float* c0_br = (const float*)d_in[6];
    const float* c0_Wo = (const float*)d_in[7];
    const float* c1_Wr = (const float*)d_in[8];
    const float* c1_br = (const float*)d_in[9];
    const float* c1_Wo = (const float*)d_in[10];
    const float* c2_Wr = (const float*)d_in[11];
    const float* c2_br = (const float*)d_in[12];
    const float* c2_Wo = (const float*)d_in[13];
    const float* c3_Wr = (const float*)d_in[14];
    const float* c3_br = (const float*)d_in[15];
    const float* c3_Wo = (const float*)d_in[16];
    const float* p_Wlin = (const float*)d_in[17];
    const float* p_blin = (const float*)d_in[18];
    const float* p_Watt = (const float*)d_in[19];
    const float* p_batt = (const float*)d_in[20];
    const float* le_W1 = (const float*)d_in[21];
    const float* le_b1 = (const float*)d_in[22];
    const float* le_W2 = (const float*)d_in[23];
    const float* le_W3 = (const float*)d_in[24];
    const float* le_b3 = (const float*)d_in[25];
    const float* lin1_W = (const float*)d_in[26];
    const float* lin1_b = (const float*)d_in[27];
    const float* pred_W = (const float*)d_in[28];
    const float* pred_b = (const float*)d_in[29];

    int E = in_sizes[2] / 2;
    const int* src = eidx;
    const int* dst = eidx + E;

    dim3 gW(8, 128);
    dim3 gWK(8, 103);
    dim3 gAdj(4, 8, BB);
    dim3 gAdjK(4, 7, BB);
    dim3 gFull(4, 8, BB);

    // ---- prologue (2 memsets total) ----
    cudaMemsetAsync(At, 0, (size_t)BB * 65536 * sizeof(float), 0);
    cudaMemsetAsync(cnt, 0, ZERO_SPAN * sizeof(float), 0);
    k_embed<<<NN, 256>>>(x_type, node_dep, emb_type, emb_dep, xa);

    // FORK 1: side runs wlq + k_w2-L0; main builds adjacency.
    cudaEventRecord(g_ev0, 0);
    cudaStreamWaitEvent(g_s2, g_ev0, 0);
    k_wlq<<<1, 256, 0, g_s2>>>(p_Wlin, p_blin, p_Watt, p_batt, wlq);
    k_w2<<<gW, 64, 0, g_s2>>>(xa, c0_Wr, c0_Wo, c0_br, Ubuf, Vbuf, NN);
    cudaEventRecord(g_ev1, g_s2);

    k_buildA<<<(E + 255) / 256, 256>>>(src, dst, At, cnt, E);

    cudaStreamWaitEvent(0, g_ev1, 0);
    k_adj<0><<<gAdj, 64>>>(At, Ubuf, Vbuf, cnt, xb, part, 0, nullptr, nullptr,
                           256, 256, 256, 65536, 65536, 256);

    // layer 1 (v = x@watt[256:] fused into epilogue)
    k_w2<<<gW, 64>>>(xb, c1_Wr, c1_Wo, c1_br, Ubuf, Vbuf, NN);
    k_adj<0><<<gAdj, 64>>>(At, Ubuf, Vbuf, cnt, xa, part, 1, p_Watt + 256, vv,
                           256, 256, 256, 65536, 65536, 256);

    // ASAP attention
    k_diag<<<BB, 256>>>(At);
    k_att<<<NN, 256>>>(At, xa, vv, wlq, St);

    // FORK 2: side computes M1full = A@S (into xb) then Z = S^T @ M1full.
    cudaEventRecord(g_ev2, 0);
    cudaStreamWaitEvent(g_s2, g_ev2, 0);
    bgemm<1, 1><<<gFull, 64, 0, g_s2>>>(At, St, xb, 256, 256, 256, 256, 256, 256,
                                        65536, 65536, 65536);
    bgemm<0, 0><<<gFull, 64, 0, g_s2>>>(St, xb, Zbuf, 256, 256, 256, 256, 256, 256,
                                        65536, 65536, 65536);

    k_xnew<<<gFull, 64>>>(St, xa, xnew, le_W1, le_W2, le_W3, av, bm, w1t);
    k_fit<<<NN / 8, 256>>>(At, av, bm, w1t, cnt, le_b1, le_b3, fit);
    k_topk<<<BB, 256>>>(fit, perm);
    cudaEventRecord(g_evT, 0);

    // side: gather A2 = Z[perm,perm] (diag := 1) + cnt2
    cudaStreamWaitEvent(g_s2, g_evT, 0);
    k_a2<<<KTOT, 256, 0, g_s2>>>(perm, Zbuf, A2, cnt2);
    cudaEventRecord(g_ev3, g_s2);

    // main: select + layer-2 weight GEMM meanwhile
    k_sel<<<KTOT, 256>>>(perm, xnew, fit, xsel);
    k_w2<<<gWK, 64>>>(xsel, c2_Wr, c2_Wo, c2_br, Ubuf, Vbuf, KTOT);

    cudaStreamWaitEvent(0, g_ev3, 0);
    k_adj<1><<<gAdjK, 64>>>(A2, Ubuf, Vbuf, cnt2, xs2, part, 2, nullptr, nullptr,
                            KPER, KPER, LD2, LD2 * LD2, KPER * 256, KPER);

    // layer 3
    k_w2<<<gWK, 64>>>(xs2, c3_Wr, c3_Wo, c3_br, Ubuf, Vbuf, KTOT);
    k_adj<1><<<gAdjK, 64>>>(A2, Ubuf, Vbuf, cnt2, xs3, part, 3, nullptr, nullptr,
                            KPER, KPER, LD2, LD2 * LD2, KPER * 256, KPER);

    k_head<<<BB, 256>>>(part, lin1_W, lin1_b, pred_W, pred_b, (float*)d_out);
}